// round 13
// baseline (speedup 1.0000x reference)
#include <cuda_runtime.h>
#include <cuda_bf16.h>
#include <cuda_fp8.h>
#include <stdint.h>
#include <math.h>

#define B_N 4096
#define D_N 2048
#define C_N 64

#define BT 128            // CTA tile M = N = 128
#define STAGES 3
#define A_TILE_B (BT*128)               // 16384 bytes (128 rows x 128B)
#define STAGE_B  (2*A_TILE_B)           // 32768 bytes
#define SMEM_TOTAL (1024 + STAGES*STAGE_B)   // 99328
#define TPAD 144          // transposed-bounce row stride (bytes, 16B multiple)

#define G1_BLOCKS 1024    // 32x32 triangular (empties exit)
#define G2_BLOCKS 512     // 32 (m) x 16 (n)

// ---------------- scratch (static device globals) ----------------
__device__ __align__(128) unsigned char g_x8[B_N * D_N];             //  8 MB e4m3(32*x_norm)
__device__ __align__(128) unsigned char g_xT8[D_N * B_N];            //  8 MB e4m3 x^T
__device__ __align__(128) unsigned char g_expS8[(size_t)B_N * B_N];  // 16 MB e4m3 expS
__device__ __align__(128) float g_R[B_N * D_N];                      // 32 MB
__device__ float g_rowsum[B_N];
__device__ float g_keep[B_N];
__device__ float g_contrib[B_N];
__device__ int   g_cnt[32];          // GEMM1 row-block readiness counters

// ---------------- PTX helpers (plain sm_80/sm_89 ISA only) ----------------
__device__ __forceinline__ uint32_t smem_u32(const void* p) {
    uint32_t a;
    asm("{ .reg .u64 t; cvta.to.shared.u64 t, %1; cvt.u32.u64 %0, t; }" : "=r"(a) : "l"(p));
    return a;
}
__device__ __forceinline__ void cp16(uint32_t s, const void* g) {
    asm volatile("cp.async.cg.shared.global [%0], [%1], 16;" :: "r"(s), "l"(g));
}
__device__ __forceinline__ void cp_commit() { asm volatile("cp.async.commit_group;"); }
__device__ __forceinline__ void cp_wait1()  { asm volatile("cp.async.wait_group 1;"); }

__device__ __forceinline__ void ldsm4(uint32_t* r, uint32_t addr) {
    asm volatile("ldmatrix.sync.aligned.m8n8.x4.shared.b16 {%0,%1,%2,%3}, [%4];"
        : "=r"(r[0]), "=r"(r[1]), "=r"(r[2]), "=r"(r[3]) : "r"(addr));
}
__device__ __forceinline__ void mma_e4m3(float* c, const uint32_t* a, uint32_t b0, uint32_t b1) {
    asm volatile(
        "mma.sync.aligned.m16n8k32.row.col.f32.e4m3.e4m3.f32 "
        "{%0,%1,%2,%3}, {%4,%5,%6,%7}, {%8,%9}, {%0,%1,%2,%3};"
        : "+f"(c[0]), "+f"(c[1]), "+f"(c[2]), "+f"(c[3])
        : "r"(a[0]), "r"(a[1]), "r"(a[2]), "r"(a[3]), "r"(b0), "r"(b1));
}
__device__ __forceinline__ uint32_t ld_acq(const int* p) {
    uint32_t v;
    asm volatile("ld.acquire.gpu.global.u32 %0, [%1];" : "=r"(v) : "l"(p) : "memory");
    return v;
}
__device__ __forceinline__ unsigned char f_to_fp8(float v) {
    return (unsigned char)__nv_cvt_float_to_fp8(v, __NV_SATFINITE, __NV_E4M3);
}
__device__ __forceinline__ float fp8_to_f(unsigned char b) {
    __half_raw h = __nv_cvt_fp8_to_halfraw(b, __NV_E4M3);
    return __half2float(*reinterpret_cast<__half*>(&h));
}

// ---------------- small kernels ----------------
__global__ void k_prep(const int* __restrict__ y, const float* __restrict__ c,
                       const int* __restrict__ fs) {
    int i = blockIdx.x * blockDim.x + threadIdx.x;
    if (i < B_N) {
        int cls = y[i];
        g_contrib[i] = c[cls];
        g_keep[i] = fs[cls] ? 0.0f : 1.0f;
        g_rowsum[i] = 0.0f;
        if (i < 32) g_cnt[i] = 0;
    }
}

// fused: LayerNorm*32 -> g_x8 (e4m3)  AND  raw-x transpose -> g_xT8 (e4m3)
__global__ __launch_bounds__(256) void k_prepx(const float* __restrict__ x) {
    __shared__ float mus[32], scs[32];
    __shared__ float tile[32][33];
    const int row0 = blockIdx.x * 32;
    const int wid = threadIdx.x >> 5, lane = threadIdx.x & 31;

    #pragma unroll
    for (int rr = 0; rr < 4; rr++) {
        int r = wid * 4 + rr;
        const float* xr = x + (size_t)(row0 + r) * D_N;
        float s = 0.f, s2 = 0.f;
        for (int d = lane; d < D_N; d += 32) {
            float v = xr[d];
            s += v; s2 += v * v;
        }
        #pragma unroll
        for (int o = 16; o > 0; o >>= 1) {
            s  += __shfl_down_sync(0xffffffffu, s, o);
            s2 += __shfl_down_sync(0xffffffffu, s2, o);
        }
        if (lane == 0) {
            float mu = s / (float)D_N;
            float var = s2 / (float)D_N - mu * mu;
            mus[r] = mu;
            scs[r] = rsqrtf(var + 1e-5f) * rsqrtf((float)D_N) * 32.0f;  // x_norm scaled by 32
        }
    }
    __syncthreads();

    const int tx = threadIdx.x & 31, ty = threadIdx.x >> 5;
    for (int ct = 0; ct < D_N / 32; ct++) {
        int c0 = ct * 32;
        #pragma unroll
        for (int i = 0; i < 32; i += 8) {
            int r = ty + i;
            float v = x[(size_t)(row0 + r) * D_N + c0 + tx];
            tile[r][tx] = v;
            float q = (v - mus[r]) * scs[r];
            g_x8[(size_t)(row0 + r) * D_N + c0 + tx] = f_to_fp8(q);
        }
        __syncthreads();
        #pragma unroll
        for (int i = 0; i < 32; i += 8)
            g_xT8[(size_t)(c0 + ty + i) * B_N + row0 + tx] = f_to_fp8(tile[tx][ty + i]);
        __syncthreads();
    }
}

// ---------------- shared fp8 GEMM mainloop (byte-addressed) ----------------
// 128-row tiles, 128B (=K128 e4m3) chunks per stage; 4x k32 mma per chunk.
template<int ROWB, int KC>
__device__ __forceinline__ void gemm_main(
    const char* __restrict__ Abase, const char* __restrict__ Bbase,
    const uint32_t* sA, const uint32_t* sB,
    float acc[4][4][4],
    const uint32_t* aoff, const uint32_t* boff,
    int lr0, int cc)
{
    #define LD(sidx, chunk) do {                                                       \
        _Pragma("unroll")                                                              \
        for (int _i = 0; _i < 4; _i++) {                                               \
            int _lr = lr0 + _i * 32;                                                   \
            uint32_t _soff = (uint32_t)(_lr * 128 + ((cc ^ (_lr & 7)) * 16));          \
            cp16(sA[sidx] + _soff, Abase + (size_t)_lr * ROWB + (chunk) * 128 + cc * 16); \
            cp16(sB[sidx] + _soff, Bbase + (size_t)_lr * ROWB + (chunk) * 128 + cc * 16); \
        }                                                                              \
    } while (0)

    #pragma unroll
    for (int p = 0; p < STAGES - 1; p++) {
        LD(p, p);
        cp_commit();
    }

    for (int c = 0; c < KC; c++) {
        cp_wait1();
        __syncthreads();
        if (c + STAGES - 1 < KC) LD((c + STAGES - 1) % STAGES, c + STAGES - 1);
        cp_commit();

        const uint32_t bufA = sA[c % STAGES];
        const uint32_t bufB = sB[c % STAGES];
        uint32_t aBase[4], bBase[2];
        #pragma unroll
        for (int im = 0; im < 4; im++) aBase[im] = bufA + aoff[im];
        #pragma unroll
        for (int ib = 0; ib < 2; ib++) bBase[ib] = bufB + boff[ib];

        #pragma unroll
        for (int kk = 0; kk < 4; kk++) {
            uint32_t a[4][4], b[2][4];
            #pragma unroll
            for (int im = 0; im < 4; im++)
                ldsm4(a[im], aBase[im] ^ (uint32_t)(kk << 5));
            #pragma unroll
            for (int ib = 0; ib < 2; ib++)
                ldsm4(b[ib], bBase[ib] ^ (uint32_t)(kk << 5));
            #pragma unroll
            for (int im = 0; im < 4; im++) {
                #pragma unroll
                for (int ib = 0; ib < 2; ib++) {
                    mma_e4m3(acc[im][ib * 2 + 0], a[im], b[ib][0], b[ib][2]);
                    mma_e4m3(acc[im][ib * 2 + 1], a[im], b[ib][1], b[ib][3]);
                }
            }
        }
    }
    #undef LD
}

// ---------------- fused GEMM1 (fp8, triangular) + GEMM2 (fp8), one launch ----------------
__global__ __launch_bounds__(256, 2) void k_fused(const float* __restrict__ x) {
    const int bid = blockIdx.x;
    const bool g1 = bid < G1_BLOCKS;
    int bm, bn;
    if (g1) {
        bm = bid >> 5; bn = bid & 31;
        if (bn < bm) return;                 // symmetry: upper triangle only
    } else {
        int b2 = bid - G1_BLOCKS;
        bm = b2 >> 4; bn = b2 & 15;          // m-major
        if (threadIdx.x == 0) {
            while (ld_acq(&g_cnt[bm]) < 32) __nanosleep(256);
        }
        __syncthreads();
    }

    extern __shared__ char smem[];
    const uint32_t smem_raw = smem_u32(smem);
    const uint32_t tiles0 = (smem_raw + 1023u) & ~1023u;
    const int t = threadIdx.x;
    const int wid = t >> 5, lane = t & 31;

    const int warp_m0 = (wid >> 2) * 64;
    const int warp_n0 = (wid & 3) * 32;
    const int rowA0 = bm * BT;
    const int rowB0 = bn * BT;

    uint32_t sA[STAGES], sB[STAGES];
    #pragma unroll
    for (int s = 0; s < STAGES; s++) {
        sA[s] = tiles0 + (uint32_t)s * STAGE_B;
        sB[s] = sA[s] + A_TILE_B;
    }

    const int lr0 = t >> 3;
    const int cc = t & 7;

    float acc[4][4][4];
    #pragma unroll
    for (int i = 0; i < 4; i++)
        #pragma unroll
        for (int j = 0; j < 4; j++)
            #pragma unroll
            for (int r = 0; r < 4; r++) acc[i][j][r] = 0.f;

    const int lrow = lane & 15;
    const int lhal = lane >> 4;
    uint32_t aoff[4], boff[2];
    #pragma unroll
    for (int im = 0; im < 4; im++) {
        int r = warp_m0 + im * 16 + lrow;
        aoff[im] = (uint32_t)(r * 128 + ((lhal ^ (r & 7)) << 4));
    }
    #pragma unroll
    for (int ib = 0; ib < 2; ib++) {
        int r = warp_n0 + ib * 16 + lrow;
        boff[ib] = (uint32_t)(r * 128 + ((lhal ^ (r & 7)) << 4));
    }

    if (g1) {
        // A = B = g_x8 (e4m3, row = 2048 B), K = 2048 -> KC = 16
        gemm_main<D_N, D_N / 128>(
            (const char*)g_x8 + (size_t)rowA0 * D_N,
            (const char*)g_x8 + (size_t)rowB0 * D_N,
            sA, sB, acc, aoff, boff, lr0, cc);
    } else {
        // A = expS8 (e4m3, row = 4096 B), B = xT8 (e4m3), K = 4096 -> KC = 32
        gemm_main<B_N, B_N / 128>(
            (const char*)g_expS8 + (size_t)rowA0 * B_N,
            (const char*)g_xT8 + (size_t)rowB0 * B_N,
            sA, sB, acc, aoff, boff, lr0, cc);
    }

    // ---- epilogue ----
    const int lq = lane >> 2;
    const int lp = lane & 3;
    int colg[4];
    #pragma unroll
    for (int j = 0; j < 4; j++)
        colg[j] = rowB0 + warp_n0 + (j >> 1) * 16 + (j & 1) * 8 + 2 * lp;

    if (g1) {
        const bool diag = (bm == bn);
        const float ksc = 1.0f / 1024.0f;     // undo (32)^2 input scaling
        __syncthreads();   // stage buffers dead; reuse as transpose bounce
        unsigned char* tsm = reinterpret_cast<unsigned char*>(smem + (tiles0 - smem_raw));

        float kp0[4], kp1[4];
        #pragma unroll
        for (int j = 0; j < 4; j++) { kp0[j] = g_keep[colg[j]]; kp1[j] = g_keep[colg[j] + 1]; }
        float cs[8];
        #pragma unroll
        for (int k2 = 0; k2 < 8; k2++) cs[k2] = 0.f;

        #pragma unroll
        for (int im = 0; im < 4; im++) {
            #pragma unroll
            for (int h = 0; h < 2; h++) {
                int row = rowA0 + warp_m0 + im * 16 + h * 8 + lq;
                float kr = g_keep[row];
                float rs = 0.f;
                #pragma unroll
                for (int j = 0; j < 4; j++) {
                    int c0 = colg[j], c1 = c0 + 1;
                    float e0 = __expf(acc[im][j][2 * h + 0] * ksc);
                    float e1 = __expf(acc[im][j][2 * h + 1] * ksc);
                    float v0 = (c0 == row ? 0.f : kp0[j]) * e0;
                    float v1 = (c1 == row ? 0.f : kp1[j]) * e1;
                    unsigned char q0 = f_to_fp8(v0);
                    unsigned char q1 = f_to_fp8(v1);
                    rs += fp8_to_f(q0) + fp8_to_f(q1);
                    *reinterpret_cast<unsigned short*>(g_expS8 + (size_t)row * B_N + c0) =
                        (unsigned short)(q0 | ((unsigned short)q1 << 8));
                    if (!diag) {
                        float t0f = (c0 == row ? 0.f : kr) * e0;
                        float t1f = (c1 == row ? 0.f : kr) * e1;
                        unsigned char qt0 = f_to_fp8(t0f);
                        unsigned char qt1 = f_to_fp8(t1f);
                        cs[2 * j]     += fp8_to_f(qt0);
                        cs[2 * j + 1] += fp8_to_f(qt1);
                        int rl = row - rowA0;
                        tsm[(c0 - rowB0) * TPAD + rl] = qt0;
                        tsm[(c1 - rowB0) * TPAD + rl] = qt1;
                    }
                }
                rs += __shfl_xor_sync(0xffffffffu, rs, 1);
                rs += __shfl_xor_sync(0xffffffffu, rs, 2);
                if (lp == 0) atomicAdd(&g_rowsum[row], rs);
            }
        }

        if (!diag) {
            #pragma unroll
            for (int k2 = 0; k2 < 8; k2++) {
                cs[k2] += __shfl_xor_sync(0xffffffffu, cs[k2], 4);
                cs[k2] += __shfl_xor_sync(0xffffffffu, cs[k2], 8);
                cs[k2] += __shfl_xor_sync(0xffffffffu, cs[k2], 16);
            }
            if (lane < 4) {
                #pragma unroll
                for (int j = 0; j < 4; j++) {
                    atomicAdd(&g_rowsum[colg[j]],     cs[2 * j]);
                    atomicAdd(&g_rowsum[colg[j] + 1], cs[2 * j + 1]);
                }
            }
            __syncthreads();
            // coalesced flush of the transposed tile (128 rows x 128 bytes)
            const int cl0 = t >> 3;          // 0..31
            const int ch = t & 7;            // 0..7 (16B chunks)
            #pragma unroll
            for (int it = 0; it < 4; it++) {
                int cl = cl0 + it * 32;
                uint4 v = *reinterpret_cast<const uint4*>(tsm + cl * TPAD + ch * 16);
                *reinterpret_cast<uint4*>(g_expS8 + (size_t)(rowB0 + cl) * B_N + rowA0 + ch * 16) = v;
            }
        }

        __threadfence();
        __syncthreads();
        if (t == 0) {
            atomicAdd(&g_cnt[bm], 1);
            if (bm != bn) atomicAdd(&g_cnt[bn], 1);
        }
    } else {
        #pragma unroll
        for (int im = 0; im < 4; im++) {
            #pragma unroll
            for (int h = 0; h < 2; h++) {
                int row = rowA0 + warp_m0 + im * 16 + h * 8 + lq;
                float ct = g_contrib[row];
                float s1 = ct / g_rowsum[row];     // fused reciprocal
                float s2 = 1.0f - ct;
                #pragma unroll
                for (int j = 0; j < 4; j++) {
                    const float2 xv = *(const float2*)(x + (size_t)row * D_N + colg[j]);
                    float2 o;
                    o.x = acc[im][j][2 * h + 0] * s1 + xv.x * s2;
                    o.y = acc[im][j][2 * h + 1] * s1 + xv.y * s2;
                    *(float2*)(g_R + (size_t)row * D_N + colg[j]) = o;
                }
            }
        }
    }
}

// ---------------- mix kernels ----------------
__global__ __launch_bounds__(256) void k_mixx(const float* __restrict__ alpha,
                                              const int* __restrict__ beta,
                                              float* __restrict__ out) {
    int idx = blockIdx.x * blockDim.x + threadIdx.x;
    const int nd4 = D_N / 4;
    if (idx < B_N * nd4) {
        int i = idx / nd4;
        int d4 = idx - i * nd4;
        float a = alpha[i];
        float na = 1.0f - a;
        int bi = beta[i];
        const float4* R4 = (const float4*)g_R;
        float4 r1 = R4[(size_t)i * nd4 + d4];
        float4 r2 = R4[(size_t)bi * nd4 + d4];
        float4 o;
        o.x = a * r1.x + na * r2.x;
        o.y = a * r1.y + na * r2.y;
        o.z = a * r1.z + na * r2.z;
        o.w = a * r1.w + na * r2.w;
        ((float4*)out)[idx] = o;
    }
}

__global__ void k_mixy(const float* __restrict__ alpha,
                       const int* __restrict__ beta,
                       const int* __restrict__ y,
                       float* __restrict__ out) {
    int idx = blockIdx.x * blockDim.x + threadIdx.x;
    if (idx < B_N * C_N) {
        int i = idx / C_N;
        int k = idx - i * C_N;
        float a = alpha[i];
        int bi = beta[i];
        float v = a * (k == y[i] ? 1.0f : 0.0f) + (1.0f - a) * (k == y[bi] ? 1.0f : 0.0f);
        out[(size_t)B_N * D_N + idx] = v;
    }
}

extern "C" void kernel_launch(void* const* d_in, const int* in_sizes, int n_in,
                              void* d_out, int out_size) {
    const float* x     = (const float*)d_in[0];
    const int*   y     = (const int*)  d_in[1];
    const float* alpha = (const float*)d_in[2];
    const int*   beta  = (const int*)  d_in[3];
    const float* c     = (const float*)d_in[4];
    const int*   fs    = (const int*)  d_in[5];
    float* out = (float*)d_out;

    cudaFuncSetAttribute(k_fused, cudaFuncAttributeMaxDynamicSharedMemorySize, SMEM_TOTAL);

    k_prep<<<(B_N + 255) / 256, 256>>>(y, c, fs);
    k_prepx<<<B_N / 32, 256>>>(x);
    k_fused<<<G1_BLOCKS + G2_BLOCKS, 256, SMEM_TOTAL>>>(x);
    k_mixx<<<(B_N * (D_N / 4) + 255) / 256, 256>>>(alpha, beta, out);
    k_mixy<<<(B_N * C_N + 255) / 256, 256>>>(alpha, beta, y, out);
}

// round 14
// speedup vs baseline: 1.1330x; 1.1330x over previous
#include <cuda_runtime.h>
#include <cuda_bf16.h>
#include <cuda_fp8.h>
#include <stdint.h>
#include <math.h>

#define B_N 4096
#define D_N 2048
#define C_N 64

#define BT 128            // CTA tile M = N = 128
#define STAGES 3
#define A_TILE_B (BT*128)               // 16384 bytes (128 rows x 128B)
#define STAGE_B  (2*A_TILE_B)           // 32768 bytes
#define SMEM_TOTAL (1024 + STAGES*STAGE_B)   // 99328
#define TPAD 136          // transposed-bounce row stride (bf16 elems)

#define G1_BLOCKS 1024    // 32x32 triangular (empties exit)
#define G2_BLOCKS 512     // 32 (m) x 16 (n)

// ---------------- scratch (static device globals; zero-initialized) ----------------
__device__ __align__(128) unsigned char g_x8[B_N * D_N];              //  8 MB e4m3(32*x_norm)
__device__ __align__(128) __nv_bfloat16 g_xTc[D_N * B_N];             // 16 MB bf16 x^T (K-compacted cols)
__device__ __align__(128) __nv_bfloat16 g_expSc[(size_t)B_N * B_N];   // 32 MB bf16 expS (K-compacted cols)
__device__ __align__(128) float g_R[B_N * D_N];                       // 32 MB
__device__ float g_rowsum[B_N];
__device__ float g_keep[B_N];
__device__ float g_contrib[B_N];
__device__ int   g_cnt[32];          // GEMM1 row-block readiness counters
__device__ int   g_rank[B_N];        // exclusive prefix sum of keep
__device__ int   g_kpad;             // padded compacted K (multiple of 128)

// ---------------- PTX helpers (plain sm_80/sm_89 ISA only) ----------------
__device__ __forceinline__ uint32_t smem_u32(const void* p) {
    uint32_t a;
    asm("{ .reg .u64 t; cvta.to.shared.u64 t, %1; cvt.u32.u64 %0, t; }" : "=r"(a) : "l"(p));
    return a;
}
__device__ __forceinline__ void cp16(uint32_t s, const void* g) {
    asm volatile("cp.async.cg.shared.global [%0], [%1], 16;" :: "r"(s), "l"(g));
}
__device__ __forceinline__ void cp_commit() { asm volatile("cp.async.commit_group;"); }
__device__ __forceinline__ void cp_wait1()  { asm volatile("cp.async.wait_group 1;"); }

__device__ __forceinline__ void ldsm4(uint32_t* r, uint32_t addr) {
    asm volatile("ldmatrix.sync.aligned.m8n8.x4.shared.b16 {%0,%1,%2,%3}, [%4];"
        : "=r"(r[0]), "=r"(r[1]), "=r"(r[2]), "=r"(r[3]) : "r"(addr));
}
__device__ __forceinline__ void mma_bf16(float* c, const uint32_t* a, uint32_t b0, uint32_t b1) {
    asm volatile(
        "mma.sync.aligned.m16n8k16.row.col.f32.bf16.bf16.f32 "
        "{%0,%1,%2,%3}, {%4,%5,%6,%7}, {%8,%9}, {%0,%1,%2,%3};"
        : "+f"(c[0]), "+f"(c[1]), "+f"(c[2]), "+f"(c[3])
        : "r"(a[0]), "r"(a[1]), "r"(a[2]), "r"(a[3]), "r"(b0), "r"(b1));
}
__device__ __forceinline__ void mma_e4m3(float* c, const uint32_t* a, uint32_t b0, uint32_t b1) {
    asm volatile(
        "mma.sync.aligned.m16n8k32.row.col.f32.e4m3.e4m3.f32 "
        "{%0,%1,%2,%3}, {%4,%5,%6,%7}, {%8,%9}, {%0,%1,%2,%3};"
        : "+f"(c[0]), "+f"(c[1]), "+f"(c[2]), "+f"(c[3])
        : "r"(a[0]), "r"(a[1]), "r"(a[2]), "r"(a[3]), "r"(b0), "r"(b1));
}
__device__ __forceinline__ uint32_t ld_acq(const int* p) {
    uint32_t v;
    asm volatile("ld.acquire.gpu.global.u32 %0, [%1];" : "=r"(v) : "l"(p) : "memory");
    return v;
}
__device__ __forceinline__ unsigned char f_to_fp8(float v) {
    return (unsigned char)__nv_cvt_float_to_fp8(v, __NV_SATFINITE, __NV_E4M3);
}

// ---------------- small kernels ----------------
__global__ void k_prep(const int* __restrict__ y, const float* __restrict__ c,
                       const int* __restrict__ fs) {
    int i = blockIdx.x * blockDim.x + threadIdx.x;
    if (i < B_N) {
        int cls = y[i];
        g_contrib[i] = c[cls];
        g_keep[i] = fs[cls] ? 0.0f : 1.0f;
        g_rowsum[i] = 0.0f;
        if (i < 32) g_cnt[i] = 0;
    }
}

// deterministic exclusive prefix sum of keep: g_rank + g_kpad
__global__ __launch_bounds__(1024) void k_scan() {
    __shared__ int wsum[32];
    const int t = threadIdx.x;
    const int base = t * 4;
    int k0 = g_keep[base + 0] > 0.f;
    int k1 = g_keep[base + 1] > 0.f;
    int k2 = g_keep[base + 2] > 0.f;
    int k3 = g_keep[base + 3] > 0.f;
    int s = k0 + k1 + k2 + k3;
    int inc = s;
    #pragma unroll
    for (int o = 1; o < 32; o <<= 1) {
        int v = __shfl_up_sync(0xffffffffu, inc, o);
        if ((t & 31) >= o) inc += v;
    }
    if ((t & 31) == 31) wsum[t >> 5] = inc;
    __syncthreads();
    if (t < 32) {
        int v = wsum[t];
        int i2 = v;
        #pragma unroll
        for (int o = 1; o < 32; o <<= 1) {
            int u = __shfl_up_sync(0xffffffffu, i2, o);
            if (t >= o) i2 += u;
        }
        wsum[t] = i2 - v;   // exclusive warp offsets
    }
    __syncthreads();
    int excl = inc - s + wsum[t >> 5];
    g_rank[base + 0] = excl;
    g_rank[base + 1] = excl + k0;
    g_rank[base + 2] = excl + k0 + k1;
    g_rank[base + 3] = excl + k0 + k1 + k2;
    if (t == 1023) {
        int tot = excl + s;
        g_kpad = ((tot + 127) >> 7) << 7;
    }
}

// fused: LayerNorm*32 -> g_x8 (e4m3)  AND  compacted raw-x transpose -> g_xTc (bf16)
__global__ __launch_bounds__(256) void k_prepx(const float* __restrict__ x) {
    __shared__ float mus[32], scs[32];
    __shared__ float tile[32][33];
    const int row0 = blockIdx.x * 32;
    const int wid = threadIdx.x >> 5, lane = threadIdx.x & 31;

    #pragma unroll
    for (int rr = 0; rr < 4; rr++) {
        int r = wid * 4 + rr;
        const float* xr = x + (size_t)(row0 + r) * D_N;
        float s = 0.f, s2 = 0.f;
        for (int d = lane; d < D_N; d += 32) {
            float v = xr[d];
            s += v; s2 += v * v;
        }
        #pragma unroll
        for (int o = 16; o > 0; o >>= 1) {
            s  += __shfl_down_sync(0xffffffffu, s, o);
            s2 += __shfl_down_sync(0xffffffffu, s2, o);
        }
        if (lane == 0) {
            float mu = s / (float)D_N;
            float var = s2 / (float)D_N - mu * mu;
            mus[r] = mu;
            scs[r] = rsqrtf(var + 1e-5f) * rsqrtf((float)D_N) * 32.0f;  // x_norm scaled by 32
        }
    }
    __syncthreads();

    const int tx = threadIdx.x & 31, ty = threadIdx.x >> 5;
    const int jcol = row0 + tx;
    const int rk = (g_keep[jcol] > 0.f) ? g_rank[jcol] : -1;   // compacted dest column
    for (int ct = 0; ct < D_N / 32; ct++) {
        int c0 = ct * 32;
        #pragma unroll
        for (int i = 0; i < 32; i += 8) {
            int r = ty + i;
            float v = x[(size_t)(row0 + r) * D_N + c0 + tx];
            tile[r][tx] = v;
            float q = (v - mus[r]) * scs[r];
            g_x8[(size_t)(row0 + r) * D_N + c0 + tx] = f_to_fp8(q);
        }
        __syncthreads();
        if (rk >= 0) {
            #pragma unroll
            for (int i = 0; i < 32; i += 8)
                g_xTc[(size_t)(c0 + ty + i) * B_N + rk] = __float2bfloat16(tile[tx][ty + i]);
        }
        __syncthreads();
    }
}

// ---------------- shared GEMM mainloop (byte-addressed, runtime KC) ----------------
template<bool FP8, int ROWB>
__device__ __forceinline__ void gemm_main(
    const char* __restrict__ Abase, const char* __restrict__ Bbase,
    const uint32_t* sA, const uint32_t* sB,
    float acc[4][4][4],
    const uint32_t* aoff, const uint32_t* boff,
    int lr0, int cc, int KC)
{
    #define LD(sidx, chunk) do {                                                       \
        _Pragma("unroll")                                                              \
        for (int _i = 0; _i < 4; _i++) {                                               \
            int _lr = lr0 + _i * 32;                                                   \
            uint32_t _soff = (uint32_t)(_lr * 128 + ((cc ^ (_lr & 7)) * 16));          \
            cp16(sA[sidx] + _soff, Abase + (size_t)_lr * ROWB + (chunk) * 128 + cc * 16); \
            cp16(sB[sidx] + _soff, Bbase + (size_t)_lr * ROWB + (chunk) * 128 + cc * 16); \
        }                                                                              \
    } while (0)

    #pragma unroll
    for (int p = 0; p < STAGES - 1; p++) {
        LD(p, p);
        cp_commit();
    }

    for (int c = 0; c < KC; c++) {
        cp_wait1();
        __syncthreads();
        if (c + STAGES - 1 < KC) LD((c + STAGES - 1) % STAGES, c + STAGES - 1);
        cp_commit();

        const uint32_t bufA = sA[c % STAGES];
        const uint32_t bufB = sB[c % STAGES];
        uint32_t aBase[4], bBase[2];
        #pragma unroll
        for (int im = 0; im < 4; im++) aBase[im] = bufA + aoff[im];
        #pragma unroll
        for (int ib = 0; ib < 2; ib++) bBase[ib] = bufB + boff[ib];

        #pragma unroll
        for (int kk = 0; kk < 4; kk++) {
            uint32_t a[4][4], b[2][4];
            #pragma unroll
            for (int im = 0; im < 4; im++)
                ldsm4(a[im], aBase[im] ^ (uint32_t)(kk << 5));
            #pragma unroll
            for (int ib = 0; ib < 2; ib++)
                ldsm4(b[ib], bBase[ib] ^ (uint32_t)(kk << 5));
            #pragma unroll
            for (int im = 0; im < 4; im++) {
                #pragma unroll
                for (int ib = 0; ib < 2; ib++) {
                    if (FP8) {
                        mma_e4m3(acc[im][ib * 2 + 0], a[im], b[ib][0], b[ib][2]);
                        mma_e4m3(acc[im][ib * 2 + 1], a[im], b[ib][1], b[ib][3]);
                    } else {
                        mma_bf16(acc[im][ib * 2 + 0], a[im], b[ib][0], b[ib][2]);
                        mma_bf16(acc[im][ib * 2 + 1], a[im], b[ib][1], b[ib][3]);
                    }
                }
            }
        }
    }
    #undef LD
}

// ---------------- fused GEMM1 (fp8, triangular) + GEMM2 (bf16, compacted K) ----------------
__global__ __launch_bounds__(256, 2) void k_fused(const float* __restrict__ x) {
    const int bid = blockIdx.x;
    const bool g1 = bid < G1_BLOCKS;
    int bm, bn;
    if (g1) {
        bm = bid >> 5; bn = bid & 31;
        if (bn < bm) return;                 // symmetry: upper triangle only
    } else {
        int b2 = bid - G1_BLOCKS;
        bm = b2 >> 4; bn = b2 & 15;          // m-major
        if (threadIdx.x == 0) {
            while (ld_acq(&g_cnt[bm]) < 32) __nanosleep(256);
        }
        __syncthreads();
    }

    extern __shared__ char smem[];
    const uint32_t smem_raw = smem_u32(smem);
    const uint32_t tiles0 = (smem_raw + 1023u) & ~1023u;
    const int t = threadIdx.x;
    const int wid = t >> 5, lane = t & 31;

    const int warp_m0 = (wid >> 2) * 64;
    const int warp_n0 = (wid & 3) * 32;
    const int rowA0 = bm * BT;
    const int rowB0 = bn * BT;

    uint32_t sA[STAGES], sB[STAGES];
    #pragma unroll
    for (int s = 0; s < STAGES; s++) {
        sA[s] = tiles0 + (uint32_t)s * STAGE_B;
        sB[s] = sA[s] + A_TILE_B;
    }

    const int lr0 = t >> 3;
    const int cc = t & 7;

    float acc[4][4][4];
    #pragma unroll
    for (int i = 0; i < 4; i++)
        #pragma unroll
        for (int j = 0; j < 4; j++)
            #pragma unroll
            for (int r = 0; r < 4; r++) acc[i][j][r] = 0.f;

    const int lrow = lane & 15;
    const int lhal = lane >> 4;
    uint32_t aoff[4], boff[2];
    #pragma unroll
    for (int im = 0; im < 4; im++) {
        int r = warp_m0 + im * 16 + lrow;
        aoff[im] = (uint32_t)(r * 128 + ((lhal ^ (r & 7)) << 4));
    }
    #pragma unroll
    for (int ib = 0; ib < 2; ib++) {
        int r = warp_n0 + ib * 16 + lrow;
        boff[ib] = (uint32_t)(r * 128 + ((lhal ^ (r & 7)) << 4));
    }

    if (g1) {
        // A = B = g_x8 (e4m3, row = 2048 B), K = 2048 -> KC = 16
        gemm_main<true, D_N>(
            (const char*)g_x8 + (size_t)rowA0 * D_N,
            (const char*)g_x8 + (size_t)rowB0 * D_N,
            sA, sB, acc, aoff, boff, lr0, cc, D_N / 128);
    } else {
        // A = expSc (bf16, row = 8192 B), B = xTc (bf16), K = Kpad -> KC = Kpad/64
        const int KC2 = g_kpad >> 6;
        gemm_main<false, 2 * B_N>(
            (const char*)g_expSc + (size_t)rowA0 * 2 * B_N,
            (const char*)g_xTc + (size_t)rowB0 * 2 * B_N,
            sA, sB, acc, aoff, boff, lr0, cc, KC2);
    }

    // ---- epilogue ----
    const int lq = lane >> 2;
    const int lp = lane & 3;
    int colg[4];
    #pragma unroll
    for (int j = 0; j < 4; j++)
        colg[j] = rowB0 + warp_n0 + (j >> 1) * 16 + (j & 1) * 8 + 2 * lp;

    if (g1) {
        const bool diag = (bm == bn);
        const float ksc = 1.0f / 1024.0f;     // undo (32)^2 input scaling
        __nv_bfloat16* tsm = reinterpret_cast<__nv_bfloat16*>(smem + (tiles0 - smem_raw));
        int* krB = reinterpret_cast<int*>(smem + (tiles0 - smem_raw) + 36864);
        int* krA = krB + 128;

        __syncthreads();   // stage buffers dead; reuse as bounce + kr staging
        if (t < 128) {
            int cB = rowB0 + t;
            krB[t] = (g_keep[cB] > 0.f) ? g_rank[cB] : -1;
            int rA = rowA0 + t;
            krA[t] = (g_keep[rA] > 0.f) ? g_rank[rA] : -1;
        }
        __syncthreads();

        float cs[8];
        #pragma unroll
        for (int k2 = 0; k2 < 8; k2++) cs[k2] = 0.f;

        #pragma unroll
        for (int im = 0; im < 4; im++) {
            #pragma unroll
            for (int h = 0; h < 2; h++) {
                int row = rowA0 + warp_m0 + im * 16 + h * 8 + lq;
                int rl = row - rowA0;
                float kr = (krA[rl] >= 0) ? 1.0f : 0.0f;
                float rs = 0.f;
                #pragma unroll
                for (int j = 0; j < 4; j++) {
                    int c0 = colg[j], c1 = c0 + 1;
                    int c0l = c0 - rowB0, c1l = c0l + 1;
                    int rk0 = krB[c0l], rk1 = krB[c1l];
                    float e0 = __expf(acc[im][j][2 * h + 0] * ksc);
                    float e1 = __expf(acc[im][j][2 * h + 1] * ksc);
                    float v0 = (rk0 >= 0 && c0 != row) ? e0 : 0.f;
                    float v1 = (rk1 >= 0 && c1 != row) ? e1 : 0.f;
                    __nv_bfloat16 b0 = __float2bfloat16(v0);
                    __nv_bfloat16 b1 = __float2bfloat16(v1);
                    rs += __bfloat162float(b0) + __bfloat162float(b1);
                    if (rk0 >= 0) g_expSc[(size_t)row * B_N + rk0] = b0;
                    if (rk1 >= 0) g_expSc[(size_t)row * B_N + rk1] = b1;
                    if (!diag) {
                        float t0f = (c0 == row ? 0.f : kr) * e0;
                        float t1f = (c1 == row ? 0.f : kr) * e1;
                        __nv_bfloat16 t0 = __float2bfloat16(t0f);
                        __nv_bfloat16 t1 = __float2bfloat16(t1f);
                        cs[2 * j]     += __bfloat162float(t0);
                        cs[2 * j + 1] += __bfloat162float(t1);
                        tsm[c0l * TPAD + rl] = t0;
                        tsm[c1l * TPAD + rl] = t1;
                    }
                }
                rs += __shfl_xor_sync(0xffffffffu, rs, 1);
                rs += __shfl_xor_sync(0xffffffffu, rs, 2);
                if (lp == 0) atomicAdd(&g_rowsum[row], rs);
            }
        }

        if (!diag) {
            #pragma unroll
            for (int k2 = 0; k2 < 8; k2++) {
                cs[k2] += __shfl_xor_sync(0xffffffffu, cs[k2], 4);
                cs[k2] += __shfl_xor_sync(0xffffffffu, cs[k2], 8);
                cs[k2] += __shfl_xor_sync(0xffffffffu, cs[k2], 16);
            }
            if (lane < 4) {
                #pragma unroll
                for (int j = 0; j < 4; j++) {
                    atomicAdd(&g_rowsum[colg[j]],     cs[2 * j]);
                    atomicAdd(&g_rowsum[colg[j] + 1], cs[2 * j + 1]);
                }
            }
            __syncthreads();
            // compacted flush of the transposed tile: row cl, kept source rows only
            const int cl = t & 127;
            const int half = t >> 7;
            __nv_bfloat16* dstrow = g_expSc + (size_t)(rowB0 + cl) * B_N;
            const __nv_bfloat16* srow = tsm + cl * TPAD;
            #pragma unroll 8
            for (int rl = half * 64; rl < half * 64 + 64; rl++) {
                int rk = krA[rl];
                if (rk >= 0) dstrow[rk] = srow[rl];
            }
        }

        __threadfence();
        __syncthreads();
        if (t == 0) {
            atomicAdd(&g_cnt[bm], 1);
            if (bm != bn) atomicAdd(&g_cnt[bn], 1);
        }
    } else {
        #pragma unroll
        for (int im = 0; im < 4; im++) {
            #pragma unroll
            for (int h = 0; h < 2; h++) {
                int row = rowA0 + warp_m0 + im * 16 + h * 8 + lq;
                float ct = g_contrib[row];
                float s1 = ct / g_rowsum[row];     // fused reciprocal
                float s2 = 1.0f - ct;
                #pragma unroll
                for (int j = 0; j < 4; j++) {
                    const float2 xv = *(const float2*)(x + (size_t)row * D_N + colg[j]);
                    float2 o;
                    o.x = acc[im][j][2 * h + 0] * s1 + xv.x * s2;
                    o.y = acc[im][j][2 * h + 1] * s1 + xv.y * s2;
                    *(float2*)(g_R + (size_t)row * D_N + colg[j]) = o;
                }
            }
        }
    }
}

// ---------------- mix kernels ----------------
__global__ __launch_bounds__(256) void k_mixx(const float* __restrict__ alpha,
                                              const int* __restrict__ beta,
                                              float* __restrict__ out) {
    int idx = blockIdx.x * blockDim.x + threadIdx.x;
    const int nd4 = D_N / 4;
    if (idx < B_N * nd4) {
        int i = idx / nd4;
        int d4 = idx - i * nd4;
        float a = alpha[i];
        float na = 1.0f - a;
        int bi = beta[i];
        const float4* R4 = (const float4*)g_R;
        float4 r1 = R4[(size_t)i * nd4 + d4];
        float4 r2 = R4[(size_t)bi * nd4 + d4];
        float4 o;
        o.x = a * r1.x + na * r2.x;
        o.y = a * r1.y + na * r2.y;
        o.z = a * r1.z + na * r2.z;
        o.w = a * r1.w + na * r2.w;
        ((float4*)out)[idx] = o;
    }
}

__global__ void k_mixy(const float* __restrict__ alpha,
                       const int* __restrict__ beta,
                       const int* __restrict__ y,
                       float* __restrict__ out) {
    int idx = blockIdx.x * blockDim.x + threadIdx.x;
    if (idx < B_N * C_N) {
        int i = idx / C_N;
        int k = idx - i * C_N;
        float a = alpha[i];
        int bi = beta[i];
        float v = a * (k == y[i] ? 1.0f : 0.0f) + (1.0f - a) * (k == y[bi] ? 1.0f : 0.0f);
        out[(size_t)B_N * D_N + idx] = v;
    }
}

extern "C" void kernel_launch(void* const* d_in, const int* in_sizes, int n_in,
                              void* d_out, int out_size) {
    const float* x     = (const float*)d_in[0];
    const int*   y     = (const int*)  d_in[1];
    const float* alpha = (const float*)d_in[2];
    const int*   beta  = (const int*)  d_in[3];
    const float* c     = (const float*)d_in[4];
    const int*   fs    = (const int*)  d_in[5];
    float* out = (float*)d_out;

    cudaFuncSetAttribute(k_fused, cudaFuncAttributeMaxDynamicSharedMemorySize, SMEM_TOTAL);

    k_prep<<<(B_N + 255) / 256, 256>>>(y, c, fs);
    k_scan<<<1, 1024>>>();
    k_prepx<<<B_N / 32, 256>>>(x);
    k_fused<<<G1_BLOCKS + G2_BLOCKS, 256, SMEM_TOTAL>>>(x);
    k_mixx<<<(B_N * (D_N / 4) + 255) / 256, 256>>>(alpha, beta, out);
    k_mixy<<<(B_N * C_N + 255) / 256, 256>>>(alpha, beta, y, out);
}

// round 15
// speedup vs baseline: 1.2068x; 1.0652x over previous
#include <cuda_runtime.h>
#include <cuda_bf16.h>
#include <cuda_fp8.h>
#include <stdint.h>
#include <math.h>

#define B_N 4096
#define D_N 2048
#define C_N 64

#define BT 128            // CTA tile M = N = 128
#define STAGES 3
#define A_TILE_B (BT*128)               // 16384 bytes (128 rows x 128B)
#define STAGE_B  (2*A_TILE_B)           // 32768 bytes
#define SMEM_TOTAL (1024 + STAGES*STAGE_B)   // 99328
#define TPAD 136          // transposed-bounce row stride (bf16 elems)

#define G1_BLOCKS 1024    // 32x32 triangular (empties exit)
#define G2_BLOCKS 512     // 32 (m) x 16 (n)

// ---------------- scratch (static device globals; zero-initialized) ----------------
__device__ __align__(128) unsigned char g_x8[B_N * D_N];              //  8 MB e4m3(32*x_norm)
__device__ __align__(128) __nv_bfloat16 g_xTc[D_N * B_N];             // 16 MB bf16 x^T (K-compacted cols)
__device__ __align__(128) __nv_bfloat16 g_expSc[(size_t)B_N * B_N];   // 32 MB bf16 expS (K-compacted cols)
__device__ __align__(128) float g_R[B_N * D_N];                       // 32 MB
__device__ float g_rowsum[B_N];
__device__ float g_keep[B_N];
__device__ float g_contrib[B_N];
__device__ float g_mu[B_N];
__device__ float g_sc[B_N];
__device__ int   g_cnt[32];          // GEMM1 row-block readiness counters
__device__ int   g_rank[B_N];        // exclusive prefix sum of keep
__device__ int   g_kpad;             // padded compacted K (multiple of 128)

// ---------------- PTX helpers (plain sm_80/sm_89 ISA only) ----------------
__device__ __forceinline__ uint32_t smem_u32(const void* p) {
    uint32_t a;
    asm("{ .reg .u64 t; cvta.to.shared.u64 t, %1; cvt.u32.u64 %0, t; }" : "=r"(a) : "l"(p));
    return a;
}
__device__ __forceinline__ void cp16(uint32_t s, const void* g) {
    asm volatile("cp.async.cg.shared.global [%0], [%1], 16;" :: "r"(s), "l"(g));
}
__device__ __forceinline__ void cp_commit() { asm volatile("cp.async.commit_group;"); }
__device__ __forceinline__ void cp_wait1()  { asm volatile("cp.async.wait_group 1;"); }

__device__ __forceinline__ void ldsm4(uint32_t* r, uint32_t addr) {
    asm volatile("ldmatrix.sync.aligned.m8n8.x4.shared.b16 {%0,%1,%2,%3}, [%4];"
        : "=r"(r[0]), "=r"(r[1]), "=r"(r[2]), "=r"(r[3]) : "r"(addr));
}
__device__ __forceinline__ void mma_bf16(float* c, const uint32_t* a, uint32_t b0, uint32_t b1) {
    asm volatile(
        "mma.sync.aligned.m16n8k16.row.col.f32.bf16.bf16.f32 "
        "{%0,%1,%2,%3}, {%4,%5,%6,%7}, {%8,%9}, {%0,%1,%2,%3};"
        : "+f"(c[0]), "+f"(c[1]), "+f"(c[2]), "+f"(c[3])
        : "r"(a[0]), "r"(a[1]), "r"(a[2]), "r"(a[3]), "r"(b0), "r"(b1));
}
__device__ __forceinline__ void mma_e4m3(float* c, const uint32_t* a, uint32_t b0, uint32_t b1) {
    asm volatile(
        "mma.sync.aligned.m16n8k32.row.col.f32.e4m3.e4m3.f32 "
        "{%0,%1,%2,%3}, {%4,%5,%6,%7}, {%8,%9}, {%0,%1,%2,%3};"
        : "+f"(c[0]), "+f"(c[1]), "+f"(c[2]), "+f"(c[3])
        : "r"(a[0]), "r"(a[1]), "r"(a[2]), "r"(a[3]), "r"(b0), "r"(b1));
}
__device__ __forceinline__ uint32_t ld_acq(const int* p) {
    uint32_t v;
    asm volatile("ld.acquire.gpu.global.u32 %0, [%1];" : "=r"(v) : "l"(p) : "memory");
    return v;
}
__device__ __forceinline__ unsigned char f_to_fp8(float v) {
    return (unsigned char)__nv_cvt_float_to_fp8(v, __NV_SATFINITE, __NV_E4M3);
}

// ---------------- k_prep: per-sample scalars + LN stats (warp per row) ----------------
__global__ __launch_bounds__(256) void k_prep(const float* __restrict__ x,
                                              const int* __restrict__ y,
                                              const float* __restrict__ c,
                                              const int* __restrict__ fs) {
    const int wid = threadIdx.x >> 5, lane = threadIdx.x & 31;
    const int row = blockIdx.x * 8 + wid;

    if (lane == 0) {
        int cls = y[row];
        g_contrib[row] = c[cls];
        g_keep[row] = fs[cls] ? 0.0f : 1.0f;
        g_rowsum[row] = 0.0f;
    }
    if (blockIdx.x == 0 && threadIdx.x < 32) g_cnt[threadIdx.x] = 0;

    const float4* xr = (const float4*)(x + (size_t)row * D_N);
    float s = 0.f, s2 = 0.f;
    #pragma unroll
    for (int it = 0; it < D_N / 128; it++) {      // 16 iters: 32 lanes * 4
        float4 v = xr[lane + it * 32];
        s  += v.x + v.y + v.z + v.w;
        s2 += v.x * v.x + v.y * v.y + v.z * v.z + v.w * v.w;
    }
    #pragma unroll
    for (int o = 16; o > 0; o >>= 1) {
        s  += __shfl_down_sync(0xffffffffu, s, o);
        s2 += __shfl_down_sync(0xffffffffu, s2, o);
    }
    if (lane == 0) {
        float mu = s / (float)D_N;
        float var = s2 / (float)D_N - mu * mu;
        g_mu[row] = mu;
        g_sc[row] = rsqrtf(var + 1e-5f) * rsqrtf((float)D_N) * 32.0f;  // x_norm scaled by 32
    }
}

// deterministic exclusive prefix sum of keep: g_rank + g_kpad
__global__ __launch_bounds__(1024) void k_scan() {
    __shared__ int wsum[32];
    const int t = threadIdx.x;
    const int base = t * 4;
    int k0 = g_keep[base + 0] > 0.f;
    int k1 = g_keep[base + 1] > 0.f;
    int k2 = g_keep[base + 2] > 0.f;
    int k3 = g_keep[base + 3] > 0.f;
    int s = k0 + k1 + k2 + k3;
    int inc = s;
    #pragma unroll
    for (int o = 1; o < 32; o <<= 1) {
        int v = __shfl_up_sync(0xffffffffu, inc, o);
        if ((t & 31) >= o) inc += v;
    }
    if ((t & 31) == 31) wsum[t >> 5] = inc;
    __syncthreads();
    if (t < 32) {
        int v = wsum[t];
        int i2 = v;
        #pragma unroll
        for (int o = 1; o < 32; o <<= 1) {
            int u = __shfl_up_sync(0xffffffffu, i2, o);
            if (t >= o) i2 += u;
        }
        wsum[t] = i2 - v;   // exclusive warp offsets
    }
    __syncthreads();
    int excl = inc - s + wsum[t >> 5];
    g_rank[base + 0] = excl;
    g_rank[base + 1] = excl + k0;
    g_rank[base + 2] = excl + k0 + k1;
    g_rank[base + 3] = excl + k0 + k1 + k2;
    if (t == 1023) {
        int tot = excl + s;
        g_kpad = ((tot + 127) >> 7) << 7;
    }
}

// fused: x_norm*32 -> g_x8 (e4m3)  AND  compacted raw-x transpose -> g_xTc (bf16)
// grid (128 row-blocks, 4 col-slices of 512)
__global__ __launch_bounds__(256) void k_prepx(const float* __restrict__ x) {
    __shared__ float mus[32], scs[32];
    __shared__ int rks[32];
    __shared__ float tile[32][33];
    const int t = threadIdx.x;
    const int row0 = blockIdx.x * 32;
    const int cs0 = blockIdx.y * 512;

    if (t < 32) {
        int r = row0 + t;
        mus[t] = g_mu[r];
        scs[t] = g_sc[r];
        rks[t] = (g_keep[r] > 0.f) ? g_rank[r] : -1;
    }
    __syncthreads();

    // phase B: fp8 writes, 32 rows x 512 cols = 4096 float4 / 256 threads = 16 iters
    #pragma unroll
    for (int it = 0; it < 16; it++) {
        int idx = t + it * 256;
        int r = idx >> 7;             // 128 float4 per row-slice
        int c4 = idx & 127;
        float4 v = *(const float4*)(x + (size_t)(row0 + r) * D_N + cs0 + c4 * 4);
        float mu = mus[r], sc = scs[r];
        uchar4 q;
        q.x = f_to_fp8((v.x - mu) * sc);
        q.y = f_to_fp8((v.y - mu) * sc);
        q.z = f_to_fp8((v.z - mu) * sc);
        q.w = f_to_fp8((v.w - mu) * sc);
        *(uchar4*)(g_x8 + (size_t)(row0 + r) * D_N + cs0 + c4 * 4) = q;
    }

    // phase C: transpose 16 col-tiles of 32x32
    const int ty = t >> 3, tx8 = t & 7;      // load indexing
    const int tx = t & 31, ty2 = t >> 5;     // store indexing
    const int rk = rks[tx];
    for (int ct = 0; ct < 16; ct++) {
        int c0 = cs0 + ct * 32;
        __syncthreads();
        float4 v = *(const float4*)(x + (size_t)(row0 + ty) * D_N + c0 + tx8 * 4);
        tile[ty][tx8 * 4 + 0] = v.x;
        tile[ty][tx8 * 4 + 1] = v.y;
        tile[ty][tx8 * 4 + 2] = v.z;
        tile[ty][tx8 * 4 + 3] = v.w;
        __syncthreads();
        if (rk >= 0) {
            #pragma unroll
            for (int i = 0; i < 4; i++) {
                int dl = ty2 + i * 8;
                g_xTc[(size_t)(c0 + dl) * B_N + rk] = __float2bfloat16(tile[tx][dl]);
            }
        }
    }
}

// ---------------- shared GEMM mainloop (byte-addressed, runtime KC) ----------------
template<bool FP8, int ROWB>
__device__ __forceinline__ void gemm_main(
    const char* __restrict__ Abase, const char* __restrict__ Bbase,
    const uint32_t* sA, const uint32_t* sB,
    float acc[4][4][4],
    const uint32_t* aoff, const uint32_t* boff,
    int lr0, int cc, int KC)
{
    #define LD(sidx, chunk) do {                                                       \
        _Pragma("unroll")                                                              \
        for (int _i = 0; _i < 4; _i++) {                                               \
            int _lr = lr0 + _i * 32;                                                   \
            uint32_t _soff = (uint32_t)(_lr * 128 + ((cc ^ (_lr & 7)) * 16));          \
            cp16(sA[sidx] + _soff, Abase + (size_t)_lr * ROWB + (chunk) * 128 + cc * 16); \
            cp16(sB[sidx] + _soff, Bbase + (size_t)_lr * ROWB + (chunk) * 128 + cc * 16); \
        }                                                                              \
    } while (0)

    #pragma unroll
    for (int p = 0; p < STAGES - 1; p++) {
        LD(p, p);
        cp_commit();
    }

    for (int c = 0; c < KC; c++) {
        cp_wait1();
        __syncthreads();
        if (c + STAGES - 1 < KC) LD((c + STAGES - 1) % STAGES, c + STAGES - 1);
        cp_commit();

        const uint32_t bufA = sA[c % STAGES];
        const uint32_t bufB = sB[c % STAGES];
        uint32_t aBase[4], bBase[2];
        #pragma unroll
        for (int im = 0; im < 4; im++) aBase[im] = bufA + aoff[im];
        #pragma unroll
        for (int ib = 0; ib < 2; ib++) bBase[ib] = bufB + boff[ib];

        #pragma unroll
        for (int kk = 0; kk < 4; kk++) {
            uint32_t a[4][4], b[2][4];
            #pragma unroll
            for (int im = 0; im < 4; im++)
                ldsm4(a[im], aBase[im] ^ (uint32_t)(kk << 5));
            #pragma unroll
            for (int ib = 0; ib < 2; ib++)
                ldsm4(b[ib], bBase[ib] ^ (uint32_t)(kk << 5));
            #pragma unroll
            for (int im = 0; im < 4; im++) {
                #pragma unroll
                for (int ib = 0; ib < 2; ib++) {
                    if (FP8) {
                        mma_e4m3(acc[im][ib * 2 + 0], a[im], b[ib][0], b[ib][2]);
                        mma_e4m3(acc[im][ib * 2 + 1], a[im], b[ib][1], b[ib][3]);
                    } else {
                        mma_bf16(acc[im][ib * 2 + 0], a[im], b[ib][0], b[ib][2]);
                        mma_bf16(acc[im][ib * 2 + 1], a[im], b[ib][1], b[ib][3]);
                    }
                }
            }
        }
    }
    #undef LD
}

// ---------------- fused GEMM1 (fp8, triangular) + GEMM2 (bf16, compacted K) ----------------
__global__ __launch_bounds__(256, 2) void k_fused(const float* __restrict__ x) {
    const int bid = blockIdx.x;
    const bool g1 = bid < G1_BLOCKS;
    int bm, bn;
    if (g1) {
        bm = bid >> 5; bn = bid & 31;
        if (bn < bm) return;                 // symmetry: upper triangle only
    } else {
        int b2 = bid - G1_BLOCKS;
        bm = b2 >> 4; bn = b2 & 15;          // m-major
        if (threadIdx.x == 0) {
            while (ld_acq(&g_cnt[bm]) < 32) __nanosleep(256);
        }
        __syncthreads();
    }

    extern __shared__ char smem[];
    const uint32_t smem_raw = smem_u32(smem);
    const uint32_t tiles0 = (smem_raw + 1023u) & ~1023u;
    const int t = threadIdx.x;
    const int wid = t >> 5, lane = t & 31;

    const int warp_m0 = (wid >> 2) * 64;
    const int warp_n0 = (wid & 3) * 32;
    const int rowA0 = bm * BT;
    const int rowB0 = bn * BT;

    uint32_t sA[STAGES], sB[STAGES];
    #pragma unroll
    for (int s = 0; s < STAGES; s++) {
        sA[s] = tiles0 + (uint32_t)s * STAGE_B;
        sB[s] = sA[s] + A_TILE_B;
    }

    const int lr0 = t >> 3;
    const int cc = t & 7;

    float acc[4][4][4];
    #pragma unroll
    for (int i = 0; i < 4; i++)
        #pragma unroll
        for (int j = 0; j < 4; j++)
            #pragma unroll
            for (int r = 0; r < 4; r++) acc[i][j][r] = 0.f;

    const int lrow = lane & 15;
    const int lhal = lane >> 4;
    uint32_t aoff[4], boff[2];
    #pragma unroll
    for (int im = 0; im < 4; im++) {
        int r = warp_m0 + im * 16 + lrow;
        aoff[im] = (uint32_t)(r * 128 + ((lhal ^ (r & 7)) << 4));
    }
    #pragma unroll
    for (int ib = 0; ib < 2; ib++) {
        int r = warp_n0 + ib * 16 + lrow;
        boff[ib] = (uint32_t)(r * 128 + ((lhal ^ (r & 7)) << 4));
    }

    if (g1) {
        gemm_main<true, D_N>(
            (const char*)g_x8 + (size_t)rowA0 * D_N,
            (const char*)g_x8 + (size_t)rowB0 * D_N,
            sA, sB, acc, aoff, boff, lr0, cc, D_N / 128);
    } else {
        const int KC2 = g_kpad >> 6;
        gemm_main<false, 2 * B_N>(
            (const char*)g_expSc + (size_t)rowA0 * 2 * B_N,
            (const char*)g_xTc + (size_t)rowB0 * 2 * B_N,
            sA, sB, acc, aoff, boff, lr0, cc, KC2);
    }

    // ---- epilogue ----
    const int lq = lane >> 2;
    const int lp = lane & 3;
    int colg[4];
    #pragma unroll
    for (int j = 0; j < 4; j++)
        colg[j] = rowB0 + warp_n0 + (j >> 1) * 16 + (j & 1) * 8 + 2 * lp;

    if (g1) {
        const bool diag = (bm == bn);
        const float ksc = 1.0f / 1024.0f;     // undo (32)^2 input scaling
        __nv_bfloat16* tsm = reinterpret_cast<__nv_bfloat16*>(smem + (tiles0 - smem_raw));
        int* krB = reinterpret_cast<int*>(smem + (tiles0 - smem_raw) + 36864);
        int* krA = krB + 128;

        __syncthreads();   // stage buffers dead; reuse as bounce + kr staging
        if (t < 128) {
            int cB = rowB0 + t;
            krB[t] = (g_keep[cB] > 0.f) ? g_rank[cB] : -1;
            int rA = rowA0 + t;
            krA[t] = (g_keep[rA] > 0.f) ? g_rank[rA] : -1;
        }
        __syncthreads();

        float cs[8];
        #pragma unroll
        for (int k2 = 0; k2 < 8; k2++) cs[k2] = 0.f;

        #pragma unroll
        for (int im = 0; im < 4; im++) {
            #pragma unroll
            for (int h = 0; h < 2; h++) {
                int row = rowA0 + warp_m0 + im * 16 + h * 8 + lq;
                int rl = row - rowA0;
                float kr = (krA[rl] >= 0) ? 1.0f : 0.0f;
                float rs = 0.f;
                #pragma unroll
                for (int j = 0; j < 4; j++) {
                    int c0 = colg[j], c1 = c0 + 1;
                    int c0l = c0 - rowB0, c1l = c0l + 1;
                    int rk0 = krB[c0l], rk1 = krB[c1l];
                    float e0 = __expf(acc[im][j][2 * h + 0] * ksc);
                    float e1 = __expf(acc[im][j][2 * h + 1] * ksc);
                    float v0 = (rk0 >= 0 && c0 != row) ? e0 : 0.f;
                    float v1 = (rk1 >= 0 && c1 != row) ? e1 : 0.f;
                    __nv_bfloat16 b0 = __float2bfloat16(v0);
                    __nv_bfloat16 b1 = __float2bfloat16(v1);
                    rs += __bfloat162float(b0) + __bfloat162float(b1);
                    if (rk0 >= 0) g_expSc[(size_t)row * B_N + rk0] = b0;
                    if (rk1 >= 0) g_expSc[(size_t)row * B_N + rk1] = b1;
                    if (!diag) {
                        float t0f = (c0 == row ? 0.f : kr) * e0;
                        float t1f = (c1 == row ? 0.f : kr) * e1;
                        __nv_bfloat16 t0 = __float2bfloat16(t0f);
                        __nv_bfloat16 t1 = __float2bfloat16(t1f);
                        cs[2 * j]     += __bfloat162float(t0);
                        cs[2 * j + 1] += __bfloat162float(t1);
                        tsm[c0l * TPAD + rl] = t0;
                        tsm[c1l * TPAD + rl] = t1;
                    }
                }
                rs += __shfl_xor_sync(0xffffffffu, rs, 1);
                rs += __shfl_xor_sync(0xffffffffu, rs, 2);
                if (lp == 0) atomicAdd(&g_rowsum[row], rs);
            }
        }

        if (!diag) {
            #pragma unroll
            for (int k2 = 0; k2 < 8; k2++) {
                cs[k2] += __shfl_xor_sync(0xffffffffu, cs[k2], 4);
                cs[k2] += __shfl_xor_sync(0xffffffffu, cs[k2], 8);
                cs[k2] += __shfl_xor_sync(0xffffffffu, cs[k2], 16);
            }
            if (lane < 4) {
                #pragma unroll
                for (int j = 0; j < 4; j++) {
                    atomicAdd(&g_rowsum[colg[j]],     cs[2 * j]);
                    atomicAdd(&g_rowsum[colg[j] + 1], cs[2 * j + 1]);
                }
            }
            __syncthreads();
            // compacted flush of the transposed tile: row cl, kept source rows only
            const int cl = t & 127;
            const int half = t >> 7;
            __nv_bfloat16* dstrow = g_expSc + (size_t)(rowB0 + cl) * B_N;
            const __nv_bfloat16* srow = tsm + cl * TPAD;
            #pragma unroll 8
            for (int rl = half * 64; rl < half * 64 + 64; rl++) {
                int rk = krA[rl];
                if (rk >= 0) dstrow[rk] = srow[rl];
            }
        }

        __threadfence();
        __syncthreads();
        if (t == 0) {
            atomicAdd(&g_cnt[bm], 1);
            if (bm != bn) atomicAdd(&g_cnt[bn], 1);
        }
    } else {
        #pragma unroll
        for (int im = 0; im < 4; im++) {
            #pragma unroll
            for (int h = 0; h < 2; h++) {
                int row = rowA0 + warp_m0 + im * 16 + h * 8 + lq;
                float ct = g_contrib[row];
                float s1 = ct / g_rowsum[row];     // fused reciprocal
                float s2 = 1.0f - ct;
                #pragma unroll
                for (int j = 0; j < 4; j++) {
                    const float2 xv = *(const float2*)(x + (size_t)row * D_N + colg[j]);
                    float2 o;
                    o.x = acc[im][j][2 * h + 0] * s1 + xv.x * s2;
                    o.y = acc[im][j][2 * h + 1] * s1 + xv.y * s2;
                    *(float2*)(g_R + (size_t)row * D_N + colg[j]) = o;
                }
            }
        }
    }
}

// ---------------- fused mix kernel (x_mix + y_mix in one launch) ----------------
__global__ __launch_bounds__(256) void k_mix(const float* __restrict__ alpha,
                                             const int* __restrict__ beta,
                                             const int* __restrict__ y,
                                             float* __restrict__ out) {
    const int nd4 = D_N / 4;
    if (blockIdx.x < 8192) {
        int idx = blockIdx.x * 256 + threadIdx.x;   // over B*D/4
        int i = idx / nd4;
        int d4 = idx - i * nd4;
        float a = alpha[i];
        float na = 1.0f - a;
        int bi = beta[i];
        const float4* R4 = (const float4*)g_R;
        float4 r1 = R4[(size_t)i * nd4 + d4];
        float4 r2 = R4[(size_t)bi * nd4 + d4];
        float4 o;
        o.x = a * r1.x + na * r2.x;
        o.y = a * r1.y + na * r2.y;
        o.z = a * r1.z + na * r2.z;
        o.w = a * r1.w + na * r2.w;
        ((float4*)out)[idx] = o;
    } else {
        int idx = (blockIdx.x - 8192) * 256 + threadIdx.x;   // over B*C
        int i = idx >> 6;
        int k = idx & 63;
        float a = alpha[i];
        int bi = beta[i];
        float v = a * (k == y[i] ? 1.0f : 0.0f) + (1.0f - a) * (k == y[bi] ? 1.0f : 0.0f);
        out[(size_t)B_N * D_N + idx] = v;
    }
}

extern "C" void kernel_launch(void* const* d_in, const int* in_sizes, int n_in,
                              void* d_out, int out_size) {
    const float* x     = (const float*)d_in[0];
    const int*   y     = (const int*)  d_in[1];
    const float* alpha = (const float*)d_in[2];
    const int*   beta  = (const int*)  d_in[3];
    const float* c     = (const float*)d_in[4];
    const int*   fs    = (const int*)  d_in[5];
    float* out = (float*)d_out;

    cudaFuncSetAttribute(k_fused, cudaFuncAttributeMaxDynamicSharedMemorySize, SMEM_TOTAL);

    k_prep<<<B_N / 8, 256>>>(x, y, c, fs);
    k_scan<<<1, 1024>>>();
    k_prepx<<<dim3(B_N / 32, 4), 256>>>(x);
    k_fused<<<G1_BLOCKS + G2_BLOCKS, 256, SMEM_TOTAL>>>(x);
    k_mix<<<8192 + (B_N * C_N) / 256, 256>>>(alpha, beta, y, out);
}

// round 16
// speedup vs baseline: 1.3532x; 1.1213x over previous
#include <cuda_runtime.h>
#include <cuda_bf16.h>
#include <cuda_fp8.h>
#include <stdint.h>
#include <math.h>

#define B_N 4096
#define D_N 2048
#define C_N 64

#define BT 128            // CTA tile M = N = 128
#define STAGES 3
#define A_TILE_B (BT*128)               // 16384 bytes (128 rows x 128B)
#define STAGE_B  (2*A_TILE_B)           // 32768 bytes
#define SMEM_TOTAL (1024 + STAGES*STAGE_B)   // 99328
#define TPAD 136          // transposed-bounce row stride (bf16 elems)

#define G1_BLOCKS 1024    // 32x32 triangular (empties exit)
#define G2_BLOCKS 512     // 32 (m) x 16 (n)

// ---------------- scratch (static device globals; zero-initialized) ----------------
__device__ __align__(128) unsigned char g_x8[B_N * D_N];              //  8 MB e4m3, PERMUTED rows
__device__ __align__(128) __nv_bfloat16 g_xTc[D_N * B_N];             // 16 MB bf16 x^T, permuted/compact cols
__device__ __align__(128) __nv_bfloat16 g_expSc[(size_t)B_N * B_N];   // 32 MB bf16 expS, permuted
__device__ __align__(128) float g_R[B_N * D_N];                       // 32 MB, permuted rows
__device__ float g_rowsum[B_N];       // permuted index
__device__ float g_keep[B_N];         // original index (scan input)
__device__ float g_contrib[B_N];      // original index
__device__ float g_contrib_p[B_N];    // permuted index
__device__ float g_mu[B_N];
__device__ float g_sc[B_N];
__device__ int   g_cnt[32];           // GEMM1 row-block readiness counters
__device__ int   g_perm[B_N];         // orig -> permuted
__device__ int   g_iperm[B_N];        // permuted -> orig
__device__ int   g_kpad;              // padded compacted K (multiple of 128)
__device__ int   g_kc;                // number of kept rows

// ---------------- PTX helpers (plain sm_80/sm_89 ISA only) ----------------
__device__ __forceinline__ uint32_t smem_u32(const void* p) {
    uint32_t a;
    asm("{ .reg .u64 t; cvta.to.shared.u64 t, %1; cvt.u32.u64 %0, t; }" : "=r"(a) : "l"(p));
    return a;
}
__device__ __forceinline__ void cp16(uint32_t s, const void* g) {
    asm volatile("cp.async.cg.shared.global [%0], [%1], 16;" :: "r"(s), "l"(g));
}
__device__ __forceinline__ void cp_commit() { asm volatile("cp.async.commit_group;"); }
__device__ __forceinline__ void cp_wait1()  { asm volatile("cp.async.wait_group 1;"); }

__device__ __forceinline__ void ldsm4(uint32_t* r, uint32_t addr) {
    asm volatile("ldmatrix.sync.aligned.m8n8.x4.shared.b16 {%0,%1,%2,%3}, [%4];"
        : "=r"(r[0]), "=r"(r[1]), "=r"(r[2]), "=r"(r[3]) : "r"(addr));
}
__device__ __forceinline__ void mma_bf16(float* c, const uint32_t* a, uint32_t b0, uint32_t b1) {
    asm volatile(
        "mma.sync.aligned.m16n8k16.row.col.f32.bf16.bf16.f32 "
        "{%0,%1,%2,%3}, {%4,%5,%6,%7}, {%8,%9}, {%0,%1,%2,%3};"
        : "+f"(c[0]), "+f"(c[1]), "+f"(c[2]), "+f"(c[3])
        : "r"(a[0]), "r"(a[1]), "r"(a[2]), "r"(a[3]), "r"(b0), "r"(b1));
}
__device__ __forceinline__ void mma_e4m3(float* c, const uint32_t* a, uint32_t b0, uint32_t b1) {
    asm volatile(
        "mma.sync.aligned.m16n8k32.row.col.f32.e4m3.e4m3.f32 "
        "{%0,%1,%2,%3}, {%4,%5,%6,%7}, {%8,%9}, {%0,%1,%2,%3};"
        : "+f"(c[0]), "+f"(c[1]), "+f"(c[2]), "+f"(c[3])
        : "r"(a[0]), "r"(a[1]), "r"(a[2]), "r"(a[3]), "r"(b0), "r"(b1));
}
__device__ __forceinline__ uint32_t ld_acq(const int* p) {
    uint32_t v;
    asm volatile("ld.acquire.gpu.global.u32 %0, [%1];" : "=r"(v) : "l"(p) : "memory");
    return v;
}
__device__ __forceinline__ unsigned char f_to_fp8(float v) {
    return (unsigned char)__nv_cvt_float_to_fp8(v, __NV_SATFINITE, __NV_E4M3);
}

// ---------------- k_prep: per-sample scalars + LN stats (warp per row) ----------------
__global__ __launch_bounds__(256) void k_prep(const float* __restrict__ x,
                                              const int* __restrict__ y,
                                              const float* __restrict__ c,
                                              const int* __restrict__ fs) {
    const int wid = threadIdx.x >> 5, lane = threadIdx.x & 31;
    const int row = blockIdx.x * 8 + wid;

    if (lane == 0) {
        int cls = y[row];
        g_contrib[row] = c[cls];
        g_keep[row] = fs[cls] ? 0.0f : 1.0f;
        g_rowsum[row] = 0.0f;
    }
    if (blockIdx.x == 0 && threadIdx.x < 32) g_cnt[threadIdx.x] = 0;

    const float4* xr = (const float4*)(x + (size_t)row * D_N);
    float s = 0.f, s2 = 0.f;
    #pragma unroll
    for (int it = 0; it < D_N / 128; it++) {
        float4 v = xr[lane + it * 32];
        s  += v.x + v.y + v.z + v.w;
        s2 += v.x * v.x + v.y * v.y + v.z * v.z + v.w * v.w;
    }
    #pragma unroll
    for (int o = 16; o > 0; o >>= 1) {
        s  += __shfl_down_sync(0xffffffffu, s, o);
        s2 += __shfl_down_sync(0xffffffffu, s2, o);
    }
    if (lane == 0) {
        float mu = s / (float)D_N;
        float var = s2 / (float)D_N - mu * mu;
        g_mu[row] = mu;
        g_sc[row] = rsqrtf(var + 1e-5f) * rsqrtf((float)D_N) * 32.0f;  // x_norm scaled by 32
    }
}

// scan keep -> perm/iperm (kept first in order, then dropped), contrib_p, kc, kpad
__global__ __launch_bounds__(1024) void k_scan() {
    __shared__ int wsum[32];
    __shared__ int s_kc;
    const int t = threadIdx.x;
    const int base = t * 4;
    int k0 = g_keep[base + 0] > 0.f;
    int k1 = g_keep[base + 1] > 0.f;
    int k2 = g_keep[base + 2] > 0.f;
    int k3 = g_keep[base + 3] > 0.f;
    int s = k0 + k1 + k2 + k3;
    int inc = s;
    #pragma unroll
    for (int o = 1; o < 32; o <<= 1) {
        int v = __shfl_up_sync(0xffffffffu, inc, o);
        if ((t & 31) >= o) inc += v;
    }
    if ((t & 31) == 31) wsum[t >> 5] = inc;
    __syncthreads();
    if (t < 32) {
        int v = wsum[t];
        int i2 = v;
        #pragma unroll
        for (int o = 1; o < 32; o <<= 1) {
            int u = __shfl_up_sync(0xffffffffu, i2, o);
            if (t >= o) i2 += u;
        }
        wsum[t] = i2 - v;   // exclusive warp offsets
    }
    __syncthreads();
    int excl = inc - s + wsum[t >> 5];
    int r0 = excl;
    int r1 = excl + k0;
    int r2 = excl + k0 + k1;
    int r3 = excl + k0 + k1 + k2;
    if (t == 1023) {
        int tot = excl + s;
        g_kc = tot;
        g_kpad = ((tot + 127) >> 7) << 7;
        s_kc = tot;
    }
    __syncthreads();
    const int Kc = s_kc;
    int p0 = k0 ? r0 : Kc + (base + 0) - r0;
    int p1 = k1 ? r1 : Kc + (base + 1) - r1;
    int p2 = k2 ? r2 : Kc + (base + 2) - r2;
    int p3 = k3 ? r3 : Kc + (base + 3) - r3;
    g_perm[base + 0] = p0; g_iperm[p0] = base + 0; g_contrib_p[p0] = g_contrib[base + 0];
    g_perm[base + 1] = p1; g_iperm[p1] = base + 1; g_contrib_p[p1] = g_contrib[base + 1];
    g_perm[base + 2] = p2; g_iperm[p2] = base + 2; g_contrib_p[p2] = g_contrib[base + 2];
    g_perm[base + 3] = p3; g_iperm[p3] = base + 3; g_contrib_p[p3] = g_contrib[base + 3];
}

// fused: x_norm*32 -> g_x8 (e4m3, PERMUTED rows)  AND  x^T -> g_xTc (kept cols compact)
// grid (128 row-blocks, 4 col-slices of 512)
__global__ __launch_bounds__(256) void k_prepx(const float* __restrict__ x) {
    __shared__ float mus[32], scs[32];
    __shared__ int prm[32];
    __shared__ float tile[32][33];
    const int t = threadIdx.x;
    const int row0 = blockIdx.x * 32;
    const int cs0 = blockIdx.y * 512;

    if (t < 32) {
        int r = row0 + t;
        mus[t] = g_mu[r];
        scs[t] = g_sc[r];
        prm[t] = g_perm[r];
    }
    __syncthreads();

    // phase B: fp8 writes to permuted rows
    #pragma unroll
    for (int it = 0; it < 16; it++) {
        int idx = t + it * 256;
        int r = idx >> 7;
        int c4 = idx & 127;
        float4 v = *(const float4*)(x + (size_t)(row0 + r) * D_N + cs0 + c4 * 4);
        float mu = mus[r], sc = scs[r];
        uchar4 q;
        q.x = f_to_fp8((v.x - mu) * sc);
        q.y = f_to_fp8((v.y - mu) * sc);
        q.z = f_to_fp8((v.z - mu) * sc);
        q.w = f_to_fp8((v.w - mu) * sc);
        *(uchar4*)(g_x8 + (size_t)prm[r] * D_N + cs0 + c4 * 4) = q;
    }

    // phase C: transpose (kept cols only -> compact/permuted col index)
    const int Kc = g_kc;
    const int ty = t >> 3, tx8 = t & 7;
    const int tx = t & 31, ty2 = t >> 5;
    const int pcol = prm[tx];
    const int rk = (pcol < Kc) ? pcol : -1;
    for (int ct = 0; ct < 16; ct++) {
        int c0 = cs0 + ct * 32;
        __syncthreads();
        float4 v = *(const float4*)(x + (size_t)(row0 + ty) * D_N + c0 + tx8 * 4);
        tile[ty][tx8 * 4 + 0] = v.x;
        tile[ty][tx8 * 4 + 1] = v.y;
        tile[ty][tx8 * 4 + 2] = v.z;
        tile[ty][tx8 * 4 + 3] = v.w;
        __syncthreads();
        if (rk >= 0) {
            #pragma unroll
            for (int i = 0; i < 4; i++) {
                int dl = ty2 + i * 8;
                g_xTc[(size_t)(c0 + dl) * B_N + rk] = __float2bfloat16(tile[tx][dl]);
            }
        }
    }
}

// ---------------- shared GEMM mainloop (byte-addressed, runtime KC) ----------------
template<bool FP8, int ROWB>
__device__ __forceinline__ void gemm_main(
    const char* __restrict__ Abase, const char* __restrict__ Bbase,
    const uint32_t* sA, const uint32_t* sB,
    float acc[4][4][4],
    const uint32_t* aoff, const uint32_t* boff,
    int lr0, int cc, int KC)
{
    #define LD(sidx, chunk) do {                                                       \
        _Pragma("unroll")                                                              \
        for (int _i = 0; _i < 4; _i++) {                                               \
            int _lr = lr0 + _i * 32;                                                   \
            uint32_t _soff = (uint32_t)(_lr * 128 + ((cc ^ (_lr & 7)) * 16));          \
            cp16(sA[sidx] + _soff, Abase + (size_t)_lr * ROWB + (chunk) * 128 + cc * 16); \
            cp16(sB[sidx] + _soff, Bbase + (size_t)_lr * ROWB + (chunk) * 128 + cc * 16); \
        }                                                                              \
    } while (0)

    #pragma unroll
    for (int p = 0; p < STAGES - 1; p++) {
        LD(p, p);
        cp_commit();
    }

    for (int c = 0; c < KC; c++) {
        cp_wait1();
        __syncthreads();
        if (c + STAGES - 1 < KC) LD((c + STAGES - 1) % STAGES, c + STAGES - 1);
        cp_commit();

        const uint32_t bufA = sA[c % STAGES];
        const uint32_t bufB = sB[c % STAGES];
        uint32_t aBase[4], bBase[2];
        #pragma unroll
        for (int im = 0; im < 4; im++) aBase[im] = bufA + aoff[im];
        #pragma unroll
        for (int ib = 0; ib < 2; ib++) bBase[ib] = bufB + boff[ib];

        #pragma unroll
        for (int kk = 0; kk < 4; kk++) {
            uint32_t a[4][4], b[2][4];
            #pragma unroll
            for (int im = 0; im < 4; im++)
                ldsm4(a[im], aBase[im] ^ (uint32_t)(kk << 5));
            #pragma unroll
            for (int ib = 0; ib < 2; ib++)
                ldsm4(b[ib], bBase[ib] ^ (uint32_t)(kk << 5));
            #pragma unroll
            for (int im = 0; im < 4; im++) {
                #pragma unroll
                for (int ib = 0; ib < 2; ib++) {
                    if (FP8) {
                        mma_e4m3(acc[im][ib * 2 + 0], a[im], b[ib][0], b[ib][2]);
                        mma_e4m3(acc[im][ib * 2 + 1], a[im], b[ib][1], b[ib][3]);
                    } else {
                        mma_bf16(acc[im][ib * 2 + 0], a[im], b[ib][0], b[ib][2]);
                        mma_bf16(acc[im][ib * 2 + 1], a[im], b[ib][1], b[ib][3]);
                    }
                }
            }
        }
    }
    #undef LD
}

// ---------------- fused GEMM1 (fp8, triangular, dead-corner skipped) + GEMM2 ----------------
__global__ __launch_bounds__(256, 2) void k_fused(const float* __restrict__ x) {
    const int bid = blockIdx.x;
    const bool g1 = bid < G1_BLOCKS;
    const int kb = g_kpad >> 7;          // number of "kept-side" 128-blocks
    int bm, bn;
    if (g1) {
        bm = bid >> 5; bn = bid & 31;
        if (bn < bm) return;             // symmetry: upper triangle only
        if (bm >= kb) return;            // both-dropped corner: contributes nothing
    } else {
        int b2 = bid - G1_BLOCKS;
        bm = b2 >> 4; bn = b2 & 15;      // m-major
        if (threadIdx.x == 0) {
            while ((int)ld_acq(&g_cnt[bm]) < kb) __nanosleep(256);
        }
        __syncthreads();
    }

    extern __shared__ char smem[];
    const uint32_t smem_raw = smem_u32(smem);
    const uint32_t tiles0 = (smem_raw + 1023u) & ~1023u;
    const int t = threadIdx.x;
    const int wid = t >> 5, lane = t & 31;

    const int warp_m0 = (wid >> 2) * 64;
    const int warp_n0 = (wid & 3) * 32;
    const int rowA0 = bm * BT;
    const int rowB0 = bn * BT;

    uint32_t sA[STAGES], sB[STAGES];
    #pragma unroll
    for (int s = 0; s < STAGES; s++) {
        sA[s] = tiles0 + (uint32_t)s * STAGE_B;
        sB[s] = sA[s] + A_TILE_B;
    }

    const int lr0 = t >> 3;
    const int cc = t & 7;

    float acc[4][4][4];
    #pragma unroll
    for (int i = 0; i < 4; i++)
        #pragma unroll
        for (int j = 0; j < 4; j++)
            #pragma unroll
            for (int r = 0; r < 4; r++) acc[i][j][r] = 0.f;

    const int lrow = lane & 15;
    const int lhal = lane >> 4;
    uint32_t aoff[4], boff[2];
    #pragma unroll
    for (int im = 0; im < 4; im++) {
        int r = warp_m0 + im * 16 + lrow;
        aoff[im] = (uint32_t)(r * 128 + ((lhal ^ (r & 7)) << 4));
    }
    #pragma unroll
    for (int ib = 0; ib < 2; ib++) {
        int r = warp_n0 + ib * 16 + lrow;
        boff[ib] = (uint32_t)(r * 128 + ((lhal ^ (r & 7)) << 4));
    }

    if (g1) {
        gemm_main<true, D_N>(
            (const char*)g_x8 + (size_t)rowA0 * D_N,
            (const char*)g_x8 + (size_t)rowB0 * D_N,
            sA, sB, acc, aoff, boff, lr0, cc, D_N / 128);
    } else {
        const int KC2 = g_kpad >> 6;
        gemm_main<false, 2 * B_N>(
            (const char*)g_expSc + (size_t)rowA0 * 2 * B_N,
            (const char*)g_xTc + (size_t)rowB0 * 2 * B_N,
            sA, sB, acc, aoff, boff, lr0, cc, KC2);
    }

    // ---- epilogue ----
    const int lq = lane >> 2;
    const int lp = lane & 3;
    int colg[4];
    #pragma unroll
    for (int j = 0; j < 4; j++)
        colg[j] = rowB0 + warp_n0 + (j >> 1) * 16 + (j & 1) * 8 + 2 * lp;

    if (g1) {
        const int Kc = g_kc;
        const bool diag = (bm == bn);
        const float ksc = 1.0f / 1024.0f;     // undo (32)^2 input scaling
        __nv_bfloat16* tsm = reinterpret_cast<__nv_bfloat16*>(smem + (tiles0 - smem_raw));
        __syncthreads();   // stage buffers dead; reuse as transpose bounce

        float cs[8];
        #pragma unroll
        for (int k2 = 0; k2 < 8; k2++) cs[k2] = 0.f;

        #pragma unroll
        for (int im = 0; im < 4; im++) {
            #pragma unroll
            for (int h = 0; h < 2; h++) {
                int row = rowA0 + warp_m0 + im * 16 + h * 8 + lq;
                int rl = row - rowA0;
                float kr = (row < Kc) ? 1.0f : 0.0f;
                float rs = 0.f;
                #pragma unroll
                for (int j = 0; j < 4; j++) {
                    int c0 = colg[j], c1 = c0 + 1;
                    int c0l = c0 - rowB0;
                    float e0 = __expf(acc[im][j][2 * h + 0] * ksc);
                    float e1 = __expf(acc[im][j][2 * h + 1] * ksc);
                    float v0 = (c0 < Kc && c0 != row) ? e0 : 0.f;
                    float v1 = (c1 < Kc && c1 != row) ? e1 : 0.f;
                    __nv_bfloat16 b0 = __float2bfloat16(v0);
                    __nv_bfloat16 b1 = __float2bfloat16(v1);
                    rs += __bfloat162float(b0) + __bfloat162float(b1);
                    __nv_bfloat162 p2(b0, b1);
                    *reinterpret_cast<uint32_t*>(g_expSc + (size_t)row * B_N + c0) =
                        *reinterpret_cast<uint32_t*>(&p2);
                    if (!diag) {
                        float t0f = (c0 == row ? 0.f : kr) * e0;
                        float t1f = (c1 == row ? 0.f : kr) * e1;
                        __nv_bfloat16 t0 = __float2bfloat16(t0f);
                        __nv_bfloat16 t1 = __float2bfloat16(t1f);
                        cs[2 * j]     += __bfloat162float(t0);
                        cs[2 * j + 1] += __bfloat162float(t1);
                        tsm[c0l * TPAD + rl] = t0;
                        tsm[(c0l + 1) * TPAD + rl] = t1;
                    }
                }
                rs += __shfl_xor_sync(0xffffffffu, rs, 1);
                rs += __shfl_xor_sync(0xffffffffu, rs, 2);
                if (lp == 0) atomicAdd(&g_rowsum[row], rs);
            }
        }

        if (!diag) {
            #pragma unroll
            for (int k2 = 0; k2 < 8; k2++) {
                cs[k2] += __shfl_xor_sync(0xffffffffu, cs[k2], 4);
                cs[k2] += __shfl_xor_sync(0xffffffffu, cs[k2], 8);
                cs[k2] += __shfl_xor_sync(0xffffffffu, cs[k2], 16);
            }
            if (lane < 4) {
                #pragma unroll
                for (int j = 0; j < 4; j++) {
                    atomicAdd(&g_rowsum[colg[j]],     cs[2 * j]);
                    atomicAdd(&g_rowsum[colg[j] + 1], cs[2 * j + 1]);
                }
            }
            __syncthreads();
            // coalesced flush of transposed tile (128 rows x 256B)
            const int cl0 = t >> 4;
            const int ch = t & 15;
            #pragma unroll
            for (int it = 0; it < 8; it++) {
                int cl = cl0 + it * 16;
                uint4 v = *reinterpret_cast<const uint4*>(tsm + cl * TPAD + ch * 8);
                *reinterpret_cast<uint4*>(g_expSc + (size_t)(rowB0 + cl) * B_N + rowA0 + ch * 8) = v;
            }
        }

        __threadfence();
        __syncthreads();
        if (t == 0) {
            if (bn < kb) atomicAdd(&g_cnt[bm], 1);   // direct cols are needed
            if (bm != bn) atomicAdd(&g_cnt[bn], 1);  // mirrored cols (bm < kb always)
        }
    } else {
        #pragma unroll
        for (int im = 0; im < 4; im++) {
            #pragma unroll
            for (int h = 0; h < 2; h++) {
                int row = rowA0 + warp_m0 + im * 16 + h * 8 + lq;
                float ct = g_contrib_p[row];
                float s1 = ct / g_rowsum[row];     // fused reciprocal
                float s2 = 1.0f - ct;
                const float* xr = x + (size_t)g_iperm[row] * D_N;
                #pragma unroll
                for (int j = 0; j < 4; j++) {
                    const float2 xv = *(const float2*)(xr + colg[j]);
                    float2 o;
                    o.x = acc[im][j][2 * h + 0] * s1 + xv.x * s2;
                    o.y = acc[im][j][2 * h + 1] * s1 + xv.y * s2;
                    *(float2*)(g_R + (size_t)row * D_N + colg[j]) = o;
                }
            }
        }
    }
}

// ---------------- fused mix kernel (x_mix + y_mix in one launch) ----------------
__global__ __launch_bounds__(256) void k_mix(const float* __restrict__ alpha,
                                             const int* __restrict__ beta,
                                             const int* __restrict__ y,
                                             float* __restrict__ out) {
    const int nd4 = D_N / 4;
    if (blockIdx.x < 8192) {
        int idx = blockIdx.x * 256 + threadIdx.x;   // over B*D/4
        int i = idx / nd4;
        int d4 = idx - i * nd4;
        float a = alpha[i];
        float na = 1.0f - a;
        int bi = beta[i];
        int pi = g_perm[i];
        int pbi = g_perm[bi];
        const float4* R4 = (const float4*)g_R;
        float4 r1 = R4[(size_t)pi * nd4 + d4];
        float4 r2 = R4[(size_t)pbi * nd4 + d4];
        float4 o;
        o.x = a * r1.x + na * r2.x;
        o.y = a * r1.y + na * r2.y;
        o.z = a * r1.z + na * r2.z;
        o.w = a * r1.w + na * r2.w;
        ((float4*)out)[idx] = o;
    } else {
        int idx = (blockIdx.x - 8192) * 256 + threadIdx.x;   // over B*C
        int i = idx >> 6;
        int k = idx & 63;
        float a = alpha[i];
        int bi = beta[i];
        float v = a * (k == y[i] ? 1.0f : 0.0f) + (1.0f - a) * (k == y[bi] ? 1.0f : 0.0f);
        out[(size_t)B_N * D_N + idx] = v;
    }
}

extern "C" void kernel_launch(void* const* d_in, const int* in_sizes, int n_in,
                              void* d_out, int out_size) {
    const float* x     = (const float*)d_in[0];
    const int*   y     = (const int*)  d_in[1];
    const float* alpha = (const float*)d_in[2];
    const int*   beta  = (const int*)  d_in[3];
    const float* c     = (const float*)d_in[4];
    const int*   fs    = (const int*)  d_in[5];
    float* out = (float*)d_out;

    cudaFuncSetAttribute(k_fused, cudaFuncAttributeMaxDynamicSharedMemorySize, SMEM_TOTAL);

    k_prep<<<B_N / 8, 256>>>(x, y, c, fs);
    k_scan<<<1, 1024>>>();
    k_prepx<<<dim3(B_N / 32, 4), 256>>>(x);
    k_fused<<<G1_BLOCKS + G2_BLOCKS, 256, SMEM_TOTAL>>>(x);
    k_mix<<<8192 + (B_N * C_N) / 256, 256>>>(alpha, beta, y, out);
}

// round 17
// speedup vs baseline: 1.3552x; 1.0014x over previous
#include <cuda_runtime.h>
#include <cuda_bf16.h>
#include <cuda_fp8.h>
#include <stdint.h>
#include <math.h>

#define B_N 4096
#define D_N 2048
#define C_N 64

#define BT 128            // CTA tile M = N = 128
#define STAGES 3
#define A_TILE_B (BT*128)               // 16384 bytes (128 rows x 128B)
#define STAGE_B  (2*A_TILE_B)           // 32768 bytes
#define SMEM_TOTAL (1024 + STAGES*STAGE_B)   // 99328
#define TPAD 136          // transposed-bounce row stride (bf16 elems)
#define PREPX_SMEM (32*513*4)           // 65664 bytes

#define G1_BLOCKS 1024    // 32x32 triangular (empties exit)
#define G2_BLOCKS 512     // 32 (m) x 16 (n)

// ---------------- scratch (static device globals; zero-initialized) ----------------
__device__ __align__(128) unsigned char g_x8[B_N * D_N];              //  8 MB e4m3, PERMUTED rows
__device__ __align__(128) __nv_bfloat16 g_xTc[D_N * B_N];             // 16 MB bf16 x^T, permuted/compact cols
__device__ __align__(128) __nv_bfloat16 g_expSc[(size_t)B_N * B_N];   // 32 MB bf16 expS, permuted
__device__ __align__(128) float g_R[B_N * D_N];                       // 32 MB, permuted rows
__device__ float g_rowsum[B_N];       // permuted index
__device__ float g_keep[B_N];         // original index (scan input)
__device__ float g_contrib[B_N];      // original index
__device__ float g_contrib_p[B_N];    // permuted index
__device__ float g_mu[B_N];
__device__ float g_sc[B_N];
__device__ int   g_cnt[32];           // GEMM1 row-block readiness counters
__device__ int   g_perm[B_N];         // orig -> permuted
__device__ int   g_iperm[B_N];        // permuted -> orig
__device__ int   g_kpad;              // padded compacted K (multiple of 128)
__device__ int   g_kc;                // number of kept rows

// ---------------- PTX helpers (plain sm_80/sm_89 ISA only) ----------------
__device__ __forceinline__ uint32_t smem_u32(const void* p) {
    uint32_t a;
    asm("{ .reg .u64 t; cvta.to.shared.u64 t, %1; cvt.u32.u64 %0, t; }" : "=r"(a) : "l"(p));
    return a;
}
__device__ __forceinline__ void cp16(uint32_t s, const void* g) {
    asm volatile("cp.async.cg.shared.global [%0], [%1], 16;" :: "r"(s), "l"(g));
}
__device__ __forceinline__ void cp_commit() { asm volatile("cp.async.commit_group;"); }
__device__ __forceinline__ void cp_wait1()  { asm volatile("cp.async.wait_group 1;"); }

__device__ __forceinline__ void ldsm4(uint32_t* r, uint32_t addr) {
    asm volatile("ldmatrix.sync.aligned.m8n8.x4.shared.b16 {%0,%1,%2,%3}, [%4];"
        : "=r"(r[0]), "=r"(r[1]), "=r"(r[2]), "=r"(r[3]) : "r"(addr));
}
__device__ __forceinline__ void mma_bf16(float* c, const uint32_t* a, uint32_t b0, uint32_t b1) {
    asm volatile(
        "mma.sync.aligned.m16n8k16.row.col.f32.bf16.bf16.f32 "
        "{%0,%1,%2,%3}, {%4,%5,%6,%7}, {%8,%9}, {%0,%1,%2,%3};"
        : "+f"(c[0]), "+f"(c[1]), "+f"(c[2]), "+f"(c[3])
        : "r"(a[0]), "r"(a[1]), "r"(a[2]), "r"(a[3]), "r"(b0), "r"(b1));
}
__device__ __forceinline__ void mma_e4m3(float* c, const uint32_t* a, uint32_t b0, uint32_t b1) {
    asm volatile(
        "mma.sync.aligned.m16n8k32.row.col.f32.e4m3.e4m3.f32 "
        "{%0,%1,%2,%3}, {%4,%5,%6,%7}, {%8,%9}, {%0,%1,%2,%3};"
        : "+f"(c[0]), "+f"(c[1]), "+f"(c[2]), "+f"(c[3])
        : "r"(a[0]), "r"(a[1]), "r"(a[2]), "r"(a[3]), "r"(b0), "r"(b1));
}
__device__ __forceinline__ uint32_t ld_acq(const int* p) {
    uint32_t v;
    asm volatile("ld.acquire.gpu.global.u32 %0, [%1];" : "=r"(v) : "l"(p) : "memory");
    return v;
}
__device__ __forceinline__ unsigned char f_to_fp8(float v) {
    return (unsigned char)__nv_cvt_float_to_fp8(v, __NV_SATFINITE, __NV_E4M3);
}

// ---------------- k_prep: scalars + LN stats (blocks 0..511) AND y_mix (blocks 512..1535) ----------------
__global__ __launch_bounds__(256) void k_prep(const float* __restrict__ x,
                                              const int* __restrict__ y,
                                              const float* __restrict__ c,
                                              const int* __restrict__ fs,
                                              const float* __restrict__ alpha,
                                              const int* __restrict__ beta,
                                              float* __restrict__ out) {
    if (blockIdx.x >= 512) {
        int idx = (blockIdx.x - 512) * 256 + threadIdx.x;   // over B*C
        int i = idx >> 6;
        int k = idx & 63;
        float a = alpha[i];
        int bi = beta[i];
        float v = a * (k == y[i] ? 1.0f : 0.0f) + (1.0f - a) * (k == y[bi] ? 1.0f : 0.0f);
        out[(size_t)B_N * D_N + idx] = v;
        return;
    }

    const int wid = threadIdx.x >> 5, lane = threadIdx.x & 31;
    const int row = blockIdx.x * 8 + wid;

    if (lane == 0) {
        int cls = y[row];
        g_contrib[row] = c[cls];
        g_keep[row] = fs[cls] ? 0.0f : 1.0f;
        g_rowsum[row] = 0.0f;
    }
    if (blockIdx.x == 0 && threadIdx.x < 32) g_cnt[threadIdx.x] = 0;

    const float4* xr = (const float4*)(x + (size_t)row * D_N);
    float s = 0.f, s2 = 0.f;
    #pragma unroll
    for (int it = 0; it < D_N / 128; it++) {
        float4 v = xr[lane + it * 32];
        s  += v.x + v.y + v.z + v.w;
        s2 += v.x * v.x + v.y * v.y + v.z * v.z + v.w * v.w;
    }
    #pragma unroll
    for (int o = 16; o > 0; o >>= 1) {
        s  += __shfl_down_sync(0xffffffffu, s, o);
        s2 += __shfl_down_sync(0xffffffffu, s2, o);
    }
    if (lane == 0) {
        float mu = s / (float)D_N;
        float var = s2 / (float)D_N - mu * mu;
        g_mu[row] = mu;
        g_sc[row] = rsqrtf(var + 1e-5f) * rsqrtf((float)D_N) * 32.0f;  // x_norm scaled by 32
    }
}

// scan keep -> perm/iperm (kept first in order, then dropped), contrib_p, kc, kpad
__global__ __launch_bounds__(1024) void k_scan() {
    __shared__ int wsum[32];
    __shared__ int s_kc;
    const int t = threadIdx.x;
    const int base = t * 4;
    int k0 = g_keep[base + 0] > 0.f;
    int k1 = g_keep[base + 1] > 0.f;
    int k2 = g_keep[base + 2] > 0.f;
    int k3 = g_keep[base + 3] > 0.f;
    int s = k0 + k1 + k2 + k3;
    int inc = s;
    #pragma unroll
    for (int o = 1; o < 32; o <<= 1) {
        int v = __shfl_up_sync(0xffffffffu, inc, o);
        if ((t & 31) >= o) inc += v;
    }
    if ((t & 31) == 31) wsum[t >> 5] = inc;
    __syncthreads();
    if (t < 32) {
        int v = wsum[t];
        int i2 = v;
        #pragma unroll
        for (int o = 1; o < 32; o <<= 1) {
            int u = __shfl_up_sync(0xffffffffu, i2, o);
            if (t >= o) i2 += u;
        }
        wsum[t] = i2 - v;   // exclusive warp offsets
    }
    __syncthreads();
    int excl = inc - s + wsum[t >> 5];
    int r0 = excl;
    int r1 = excl + k0;
    int r2 = excl + k0 + k1;
    int r3 = excl + k0 + k1 + k2;
    if (t == 1023) {
        int tot = excl + s;
        g_kc = tot;
        g_kpad = ((tot + 127) >> 7) << 7;
        s_kc = tot;
    }
    __syncthreads();
    const int Kc = s_kc;
    int p0 = k0 ? r0 : Kc + (base + 0) - r0;
    int p1 = k1 ? r1 : Kc + (base + 1) - r1;
    int p2 = k2 ? r2 : Kc + (base + 2) - r2;
    int p3 = k3 ? r3 : Kc + (base + 3) - r3;
    g_perm[base + 0] = p0; g_iperm[p0] = base + 0; g_contrib_p[p0] = g_contrib[base + 0];
    g_perm[base + 1] = p1; g_iperm[p1] = base + 1; g_contrib_p[p1] = g_contrib[base + 1];
    g_perm[base + 2] = p2; g_iperm[p2] = base + 2; g_contrib_p[p2] = g_contrib[base + 2];
    g_perm[base + 3] = p3; g_iperm[p3] = base + 3; g_contrib_p[p3] = g_contrib[base + 3];
}

// fused single-read prepx: x slice staged in smem; fp8 (permuted rows) + bf16 transpose (kept cols)
// grid (128 row-blocks, 4 col-slices of 512)
__global__ __launch_bounds__(256) void k_prepx(const float* __restrict__ x) {
    extern __shared__ float sl[];          // [32][513]
    __shared__ float mus[32], scs[32];
    __shared__ int prm[32];
    const int t = threadIdx.x;
    const int row0 = blockIdx.x * 32;
    const int cs0 = blockIdx.y * 512;

    if (t < 32) {
        int r = row0 + t;
        mus[t] = g_mu[r];
        scs[t] = g_sc[r];
        prm[t] = g_perm[r];
    }
    __syncthreads();

    // phase B: single gmem read; fp8 write (permuted rows) + smem stage
    #pragma unroll
    for (int it = 0; it < 16; it++) {
        int idx = t + it * 256;
        int r = idx >> 7;             // 0..31
        int c4 = idx & 127;           // 0..127
        float4 v = *(const float4*)(x + (size_t)(row0 + r) * D_N + cs0 + c4 * 4);
        float mu = mus[r], sc = scs[r];
        uchar4 q;
        q.x = f_to_fp8((v.x - mu) * sc);
        q.y = f_to_fp8((v.y - mu) * sc);
        q.z = f_to_fp8((v.z - mu) * sc);
        q.w = f_to_fp8((v.w - mu) * sc);
        *(uchar4*)(g_x8 + (size_t)prm[r] * D_N + cs0 + c4 * 4) = q;
        float* srow = sl + r * 513 + c4 * 4;
        srow[0] = v.x; srow[1] = v.y; srow[2] = v.z; srow[3] = v.w;
    }
    __syncthreads();

    // phase C: transpose from smem (kept cols only)
    const int Kc = g_kc;
    const int tx = t & 31, ty2 = t >> 5;
    const int pcol = prm[tx];
    if (pcol < Kc) {
        const float* srow = sl + tx * 513;
        #pragma unroll 8
        for (int i = 0; i < 64; i++) {
            int dl = ty2 + i * 8;
            g_xTc[(size_t)(cs0 + dl) * B_N + pcol] = __float2bfloat16(srow[dl]);
        }
    }
}

// ---------------- shared GEMM mainloop (byte-addressed, runtime KC) ----------------
template<bool FP8, int ROWB>
__device__ __forceinline__ void gemm_main(
    const char* __restrict__ Abase, const char* __restrict__ Bbase,
    const uint32_t* sA, const uint32_t* sB,
    float acc[4][4][4],
    const uint32_t* aoff, const uint32_t* boff,
    int lr0, int cc, int KC)
{
    #define LD(sidx, chunk) do {                                                       \
        _Pragma("unroll")                                                              \
        for (int _i = 0; _i < 4; _i++) {                                               \
            int _lr = lr0 + _i * 32;                                                   \
            uint32_t _soff = (uint32_t)(_lr * 128 + ((cc ^ (_lr & 7)) * 16));          \
            cp16(sA[sidx] + _soff, Abase + (size_t)_lr * ROWB + (chunk) * 128 + cc * 16); \
            cp16(sB[sidx] + _soff, Bbase + (size_t)_lr * ROWB + (chunk) * 128 + cc * 16); \
        }                                                                              \
    } while (0)

    #pragma unroll
    for (int p = 0; p < STAGES - 1; p++) {
        LD(p, p);
        cp_commit();
    }

    for (int c = 0; c < KC; c++) {
        cp_wait1();
        __syncthreads();
        if (c + STAGES - 1 < KC) LD((c + STAGES - 1) % STAGES, c + STAGES - 1);
        cp_commit();

        const uint32_t bufA = sA[c % STAGES];
        const uint32_t bufB = sB[c % STAGES];
        uint32_t aBase[4], bBase[2];
        #pragma unroll
        for (int im = 0; im < 4; im++) aBase[im] = bufA + aoff[im];
        #pragma unroll
        for (int ib = 0; ib < 2; ib++) bBase[ib] = bufB + boff[ib];

        #pragma unroll
        for (int kk = 0; kk < 4; kk++) {
            uint32_t a[4][4], b[2][4];
            #pragma unroll
            for (int im = 0; im < 4; im++)
                ldsm4(a[im], aBase[im] ^ (uint32_t)(kk << 5));
            #pragma unroll
            for (int ib = 0; ib < 2; ib++)
                ldsm4(b[ib], bBase[ib] ^ (uint32_t)(kk << 5));
            #pragma unroll
            for (int im = 0; im < 4; im++) {
                #pragma unroll
                for (int ib = 0; ib < 2; ib++) {
                    if (FP8) {
                        mma_e4m3(acc[im][ib * 2 + 0], a[im], b[ib][0], b[ib][2]);
                        mma_e4m3(acc[im][ib * 2 + 1], a[im], b[ib][1], b[ib][3]);
                    } else {
                        mma_bf16(acc[im][ib * 2 + 0], a[im], b[ib][0], b[ib][2]);
                        mma_bf16(acc[im][ib * 2 + 1], a[im], b[ib][1], b[ib][3]);
                    }
                }
            }
        }
    }
    #undef LD
}

// ---------------- fused GEMM1 (fp8, triangular, dead-corner skipped) + GEMM2 ----------------
__global__ __launch_bounds__(256, 2) void k_fused(const float* __restrict__ x) {
    const int bid = blockIdx.x;
    const bool g1 = bid < G1_BLOCKS;
    const int kb = g_kpad >> 7;          // number of "kept-side" 128-blocks
    int bm, bn;
    if (g1) {
        bm = bid >> 5; bn = bid & 31;
        if (bn < bm) return;             // symmetry: upper triangle only
        if (bm >= kb) return;            // both-dropped corner: contributes nothing
    } else {
        int b2 = bid - G1_BLOCKS;
        bm = b2 >> 4; bn = b2 & 15;      // m-major
        if (threadIdx.x == 0) {
            while ((int)ld_acq(&g_cnt[bm]) < kb) __nanosleep(256);
        }
        __syncthreads();
    }

    extern __shared__ char smem[];
    const uint32_t smem_raw = smem_u32(smem);
    const uint32_t tiles0 = (smem_raw + 1023u) & ~1023u;
    const int t = threadIdx.x;
    const int wid = t >> 5, lane = t & 31;

    const int warp_m0 = (wid >> 2) * 64;
    const int warp_n0 = (wid & 3) * 32;
    const int rowA0 = bm * BT;
    const int rowB0 = bn * BT;

    uint32_t sA[STAGES], sB[STAGES];
    #pragma unroll
    for (int s = 0; s < STAGES; s++) {
        sA[s] = tiles0 + (uint32_t)s * STAGE_B;
        sB[s] = sA[s] + A_TILE_B;
    }

    const int lr0 = t >> 3;
    const int cc = t & 7;

    float acc[4][4][4];
    #pragma unroll
    for (int i = 0; i < 4; i++)
        #pragma unroll
        for (int j = 0; j < 4; j++)
            #pragma unroll
            for (int r = 0; r < 4; r++) acc[i][j][r] = 0.f;

    const int lrow = lane & 15;
    const int lhal = lane >> 4;
    uint32_t aoff[4], boff[2];
    #pragma unroll
    for (int im = 0; im < 4; im++) {
        int r = warp_m0 + im * 16 + lrow;
        aoff[im] = (uint32_t)(r * 128 + ((lhal ^ (r & 7)) << 4));
    }
    #pragma unroll
    for (int ib = 0; ib < 2; ib++) {
        int r = warp_n0 + ib * 16 + lrow;
        boff[ib] = (uint32_t)(r * 128 + ((lhal ^ (r & 7)) << 4));
    }

    if (g1) {
        gemm_main<true, D_N>(
            (const char*)g_x8 + (size_t)rowA0 * D_N,
            (const char*)g_x8 + (size_t)rowB0 * D_N,
            sA, sB, acc, aoff, boff, lr0, cc, D_N / 128);
    } else {
        const int KC2 = g_kpad >> 6;
        gemm_main<false, 2 * B_N>(
            (const char*)g_expSc + (size_t)rowA0 * 2 * B_N,
            (const char*)g_xTc + (size_t)rowB0 * 2 * B_N,
            sA, sB, acc, aoff, boff, lr0, cc, KC2);
    }

    // ---- epilogue ----
    const int lq = lane >> 2;
    const int lp = lane & 3;
    int colg[4];
    #pragma unroll
    for (int j = 0; j < 4; j++)
        colg[j] = rowB0 + warp_n0 + (j >> 1) * 16 + (j & 1) * 8 + 2 * lp;

    if (g1) {
        const int Kc = g_kc;
        const bool diag = (bm == bn);
        const float ksc = 1.0f / 1024.0f;     // undo (32)^2 input scaling
        __nv_bfloat16* tsm = reinterpret_cast<__nv_bfloat16*>(smem + (tiles0 - smem_raw));
        __syncthreads();   // stage buffers dead; reuse as transpose bounce

        float cs[8];
        #pragma unroll
        for (int k2 = 0; k2 < 8; k2++) cs[k2] = 0.f;

        #pragma unroll
        for (int im = 0; im < 4; im++) {
            #pragma unroll
            for (int h = 0; h < 2; h++) {
                int row = rowA0 + warp_m0 + im * 16 + h * 8 + lq;
                int rl = row - rowA0;
                float kr = (row < Kc) ? 1.0f : 0.0f;
                float rs = 0.f;
                #pragma unroll
                for (int j = 0; j < 4; j++) {
                    int c0 = colg[j], c1 = c0 + 1;
                    int c0l = c0 - rowB0;
                    float e0 = __expf(acc[im][j][2 * h + 0] * ksc);
                    float e1 = __expf(acc[im][j][2 * h + 1] * ksc);
                    float v0 = (c0 < Kc && c0 != row) ? e0 : 0.f;
                    float v1 = (c1 < Kc && c1 != row) ? e1 : 0.f;
                    __nv_bfloat16 b0 = __float2bfloat16(v0);
                    __nv_bfloat16 b1 = __float2bfloat16(v1);
                    rs += __bfloat162float(b0) + __bfloat162float(b1);
                    __nv_bfloat162 p2(b0, b1);
                    *reinterpret_cast<uint32_t*>(g_expSc + (size_t)row * B_N + c0) =
                        *reinterpret_cast<uint32_t*>(&p2);
                    if (!diag) {
                        float t0f = (c0 == row ? 0.f : kr) * e0;
                        float t1f = (c1 == row ? 0.f : kr) * e1;
                        __nv_bfloat16 t0 = __float2bfloat16(t0f);
                        __nv_bfloat16 t1 = __float2bfloat16(t1f);
                        cs[2 * j]     += __bfloat162float(t0);
                        cs[2 * j + 1] += __bfloat162float(t1);
                        tsm[c0l * TPAD + rl] = t0;
                        tsm[(c0l + 1) * TPAD + rl] = t1;
                    }
                }
                rs += __shfl_xor_sync(0xffffffffu, rs, 1);
                rs += __shfl_xor_sync(0xffffffffu, rs, 2);
                if (lp == 0) atomicAdd(&g_rowsum[row], rs);
            }
        }

        if (!diag) {
            #pragma unroll
            for (int k2 = 0; k2 < 8; k2++) {
                cs[k2] += __shfl_xor_sync(0xffffffffu, cs[k2], 4);
                cs[k2] += __shfl_xor_sync(0xffffffffu, cs[k2], 8);
                cs[k2] += __shfl_xor_sync(0xffffffffu, cs[k2], 16);
            }
            if (lane < 4) {
                #pragma unroll
                for (int j = 0; j < 4; j++) {
                    atomicAdd(&g_rowsum[colg[j]],     cs[2 * j]);
                    atomicAdd(&g_rowsum[colg[j] + 1], cs[2 * j + 1]);
                }
            }
            __syncthreads();
            // coalesced flush of transposed tile (128 rows x 256B)
            const int cl0 = t >> 4;
            const int ch = t & 15;
            #pragma unroll
            for (int it = 0; it < 8; it++) {
                int cl = cl0 + it * 16;
                uint4 v = *reinterpret_cast<const uint4*>(tsm + cl * TPAD + ch * 8);
                *reinterpret_cast<uint4*>(g_expSc + (size_t)(rowB0 + cl) * B_N + rowA0 + ch * 8) = v;
            }
        }

        __threadfence();
        __syncthreads();
        if (t == 0) {
            if (bn < kb) atomicAdd(&g_cnt[bm], 1);   // direct cols are needed
            if (bm != bn) atomicAdd(&g_cnt[bn], 1);  // mirrored cols (bm < kb always)
        }
    } else {
        #pragma unroll
        for (int im = 0; im < 4; im++) {
            #pragma unroll
            for (int h = 0; h < 2; h++) {
                int row = rowA0 + warp_m0 + im * 16 + h * 8 + lq;
                float ct = g_contrib_p[row];
                float s1 = ct / g_rowsum[row];     // fused reciprocal
                float s2 = 1.0f - ct;
                const float* xr = x + (size_t)g_iperm[row] * D_N;
                #pragma unroll
                for (int j = 0; j < 4; j++) {
                    const float2 xv = *(const float2*)(xr + colg[j]);
                    float2 o;
                    o.x = acc[im][j][2 * h + 0] * s1 + xv.x * s2;
                    o.y = acc[im][j][2 * h + 1] * s1 + xv.y * s2;
                    *(float2*)(g_R + (size_t)row * D_N + colg[j]) = o;
                }
            }
        }
    }
}

// ---------------- x_mix kernel (y_mix moved into k_prep) ----------------
__global__ __launch_bounds__(256) void k_mix(const float* __restrict__ alpha,
                                             const int* __restrict__ beta,
                                             float* __restrict__ out) {
    const int nd4 = D_N / 4;
    int idx = blockIdx.x * 256 + threadIdx.x;   // over B*D/4
    int i = idx / nd4;
    int d4 = idx - i * nd4;
    float a = alpha[i];
    float na = 1.0f - a;
    int bi = beta[i];
    int pi = g_perm[i];
    int pbi = g_perm[bi];
    const float4* R4 = (const float4*)g_R;
    float4 r1 = R4[(size_t)pi * nd4 + d4];
    float4 r2 = R4[(size_t)pbi * nd4 + d4];
    float4 o;
    o.x = a * r1.x + na * r2.x;
    o.y = a * r1.y + na * r2.y;
    o.z = a * r1.z + na * r2.z;
    o.w = a * r1.w + na * r2.w;
    ((float4*)out)[idx] = o;
}

extern "C" void kernel_launch(void* const* d_in, const int* in_sizes, int n_in,
                              void* d_out, int out_size) {
    const float* x     = (const float*)d_in[0];
    const int*   y     = (const int*)  d_in[1];
    const float* alpha = (const float*)d_in[2];
    const int*   beta  = (const int*)  d_in[3];
    const float* c     = (const float*)d_in[4];
    const int*   fs    = (const int*)  d_in[5];
    float* out = (float*)d_out;

    cudaFuncSetAttribute(k_fused, cudaFuncAttributeMaxDynamicSharedMemorySize, SMEM_TOTAL);
    cudaFuncSetAttribute(k_prepx, cudaFuncAttributeMaxDynamicSharedMemorySize, PREPX_SMEM);

    k_prep<<<512 + (B_N * C_N) / 256, 256>>>(x, y, c, fs, alpha, beta, out);
    k_scan<<<1, 1024>>>();
    k_prepx<<<dim3(B_N / 32, 4), 256, PREPX_SMEM>>>(x);
    k_fused<<<G1_BLOCKS + G2_BLOCKS, 256, SMEM_TOTAL>>>(x);
    k_mix<<<(B_N * D_N / 4) / 256, 256>>>(alpha, beta, out);
}